// round 11
// baseline (speedup 1.0000x reference)
#include <cuda_runtime.h>

// Problem constants
constexpr int BATCH = 128;
constexpr int TSEQ  = 512;
constexpr int KIN   = 906;
constexpr int NG    = 16;       // 4*H gates
constexpr int KLEN0 = 456;      // half 0: k in [0,456)   (even -> 8B aligned)
constexpr int KLEN1 = 450;      // half 1: k in [456,906) (456 even -> 8B aligned)
constexpr int CK    = 16;       // k per chunk
constexpr int NCH   = 29;       // chunks per half (28 full + remainder)
constexpr int PROWS = 256;      // rows per proj block
constexpr int F2P   = 9;        // tile pitch in float2 (lane-bank stride 18 -> conflict-free)

// Scratch (device globals; no allocation allowed)
// K-half partials, layout [t][b][j][ifgo]; i/f/o pre-scaled 0.5 (sigmoid fold)
__device__ __align__(16) float g_xph[2][BATCH * TSEQ * NG];
__device__ float g_hf[BATCH * 4];

// ---------- packed fp32x2 helpers (Blackwell FFMA2) ----------
__device__ __forceinline__ unsigned long long pack2(float x) {
    unsigned long long r;
    asm("mov.b64 %0, {%1, %1};" : "=l"(r) : "f"(x));
    return r;
}
__device__ __forceinline__ unsigned long long fma2(unsigned long long a,
                                                   unsigned long long b,
                                                   unsigned long long c) {
    unsigned long long d;
    asm("fma.rn.f32x2 %0, %1, %2, %3;" : "=l"(d) : "l"(a), "l"(b), "l"(c));
    return d;
}
__device__ __forceinline__ void unpack2(unsigned long long a, float& lo, float& hi) {
    asm("mov.b64 {%0, %1}, %2;" : "=f"(lo), "=f"(hi) : "l"(a));
}

// ---------- activations ----------
__device__ __forceinline__ float tanha(float x) {
    float r;
    asm("tanh.approx.f32 %0, %1;" : "=f"(r) : "f"(x));
    return r;
}
__device__ __forceinline__ float sigmoid_acc(float x) {
    float e = __expf(-x);
    return __fdividef(1.0f, 1.0f + e);
}
__device__ __forceinline__ float tanh_acc(float x) {
    float e = __expf(2.0f * x);
    return 1.0f - __fdividef(2.0f, 1.0f + e);
}

// ---------- cp.async ----------
__device__ __forceinline__ void cp16(void* dst, const void* src) {
    unsigned d = (unsigned)__cvta_generic_to_shared(dst);
    asm volatile("cp.async.cg.shared.global [%0], [%1], 16;" :: "r"(d), "l"(src));
}
__device__ __forceinline__ void cp8(void* dst, const void* src) {
    unsigned d = (unsigned)__cvta_generic_to_shared(dst);
    asm volatile("cp.async.ca.shared.global [%0], [%1], 8;" :: "r"(d), "l"(src));
}
__device__ __forceinline__ void cp4a(void* dst, const void* src) {
    unsigned d = (unsigned)__cvta_generic_to_shared(dst);
    asm volatile("cp.async.ca.shared.global [%0], [%1], 4;" :: "r"(d), "l"(src));
}
__device__ __forceinline__ void cp_commit() { asm volatile("cp.async.commit_group;"); }
__device__ __forceinline__ void cp_wait1()  { asm volatile("cp.async.wait_group 1;" ::: "memory"); }
__device__ __forceinline__ void cp_wait0()  { asm volatile("cp.async.wait_group 0;" ::: "memory"); }

// =====================================================================
// Kernel 1: projection. grid (256, 2); 128 threads; R=2 rows/thread.
// ALL staging via cp.async (no staging registers, no LDG/STS):
//  - x: 8B cp.async into even/odd row planes [buf][plane][r2][F2P]
//  - W: raw 4B cp.async; sigmoid 0.5-fold applied at epilogue
// Depth-2 via commit groups; ~70 regs + 39 KB smem -> 5 blocks/SM
// -> all 512 blocks resident (single wave).
// =====================================================================
__global__ __launch_bounds__(128) void proj_kernel(const float* __restrict__ x,
                                                   const float* __restrict__ Wih,
                                                   const float* __restrict__ bih,
                                                   const float* __restrict__ bhh) {
    __shared__ __align__(16) float2 stile[2][2][128][F2P];  // [buf][plane][r2][f2] 36 KB
    __shared__ __align__(16) float  sw[2][CK * 16];         // [buf][k*16+g] raw W, 2 KB

    const int tid  = threadIdx.x;
    const int lane = tid & 31;
    const int wid  = tid >> 5;
    const int half = blockIdx.y;
    const int kb   = half ? KLEN0 : 0;
    const int len  = half ? KLEN1 : KLEN0;
    const size_t row0 = (size_t)blockIdx.x * PROWS;
    const int npair_last = half ? 1 : 4;    // valid k-pairs in chunk 28

    unsigned long long accA[8], accB[8];    // [gate-pair]; A = even row, B = odd row
#pragma unroll
    for (int m = 0; m < 8; ++m) { accA[m] = 0ull; accB[m] = 0ull; }

    // ---- async staging of one 16-k chunk ----
    const int f2   = lane & 7;      // float2 slot within chunk
    const int rsub = lane >> 3;     // row sub 0..3
    auto issue_chunk = [&](int ch, int buf) {
        const int kx = min(ch * CK + 2 * f2, len - 2);   // clamped (OOB never computed)
#pragma unroll
        for (int i = 0; i < 16; ++i) {
            const int row = wid * 64 + i * 4 + rsub;
            const float* src = x + (row0 + row) * KIN + kb + kx;
            cp8(&stile[buf][row & 1][row >> 1][f2], src);
        }
#pragma unroll
        for (int u = 0; u < 2; ++u) {
            const int idx = tid + 128 * u;               // idx = kw*16 + g
            const int kw = idx >> 4, g = idx & 15;
            const int kwl = min(ch * CK + kw, len - 1);  // clamped
            cp4a(&sw[buf][idx], Wih + (size_t)g * KIN + kb + kwl);
        }
    };

    // ---- compute npairs k-pairs from buffer buf ----
    auto compute = [&](int buf, int npairs) {
        const float2* pe = &stile[buf][0][tid][0];
        const float2* po = &stile[buf][1][tid][0];
        const float* swp = sw[buf];
#pragma unroll
        for (int kp = 0; kp < 8; ++kp) {
            if (kp >= npairs) break;
            const float2 xA = pe[kp];
            const float2 xB = po[kp];
#pragma unroll
            for (int s = 0; s < 2; ++s) {
                const unsigned long long xa = pack2(s ? xA.y : xA.x);
                const unsigned long long xb = pack2(s ? xB.y : xB.x);
                const ulonglong2* wp = (const ulonglong2*)(swp + (2 * kp + s) * 16);
                ulonglong2 w0 = wp[0], w1 = wp[1];
                accA[0] = fma2(xa, w0.x, accA[0]);  accB[0] = fma2(xb, w0.x, accB[0]);
                accA[1] = fma2(xa, w0.y, accA[1]);  accB[1] = fma2(xb, w0.y, accB[1]);
                accA[2] = fma2(xa, w1.x, accA[2]);  accB[2] = fma2(xb, w1.x, accB[2]);
                accA[3] = fma2(xa, w1.y, accA[3]);  accB[3] = fma2(xb, w1.y, accB[3]);
                ulonglong2 w2 = wp[2], w3 = wp[3];
                accA[4] = fma2(xa, w2.x, accA[4]);  accB[4] = fma2(xb, w2.x, accB[4]);
                accA[5] = fma2(xa, w2.y, accA[5]);  accB[5] = fma2(xb, w2.y, accB[5]);
                accA[6] = fma2(xa, w3.x, accA[6]);  accB[6] = fma2(xb, w3.x, accB[6]);
                accA[7] = fma2(xa, w3.y, accA[7]);  accB[7] = fma2(xb, w3.y, accB[7]);
            }
        }
    };

    // ---- depth-2 pipeline ----
    issue_chunk(0, 0); cp_commit();
    issue_chunk(1, 1); cp_commit();
    cp_wait1();                      // chunk 0 complete
    __syncthreads();

#pragma unroll 1
    for (int ch = 0; ch < NCH; ++ch) {
        const int buf = ch & 1;
        if (ch < NCH - 1) compute(buf, 8);
        else              compute(buf, npair_last);
        __syncthreads();             // all warps done reading buf
        if (ch + 2 < NCH) {
            issue_chunk(ch + 2, buf); cp_commit();
            cp_wait1();              // chunk ch+1 complete
        } else {
            cp_wait0();              // drain
        }
        __syncthreads();
    }

    // ---- epilogue: unpack, 0.5-fold i/f/o, bias (half 0), store [t][b][j][ifgo] ----
    float va[16], vb[16];
#pragma unroll
    for (int m = 0; m < 8; ++m) { unpack2(accA[m], va[2*m], va[2*m+1]);
                                  unpack2(accB[m], vb[2*m], vb[2*m+1]); }
#pragma unroll
    for (int g = 0; g < 16; ++g) {
        const float sc = (g >= 8 && g < 12) ? 1.0f : 0.5f;
        if (half == 0) {
            const float b = __ldg(&bih[g]) + __ldg(&bhh[g]);
            va[g] = sc * (va[g] + b);
            vb[g] = sc * (vb[g] + b);
        } else {
            va[g] *= sc;
            vb[g] *= sc;
        }
    }

    float4* dst = reinterpret_cast<float4*>(g_xph[half]);
    const size_t rA = row0 + 2 * tid;
    const size_t tA = rA & 511, bA = rA >> 9;
    const size_t tB = (rA + 1) & 511, bB = (rA + 1) >> 9;
#pragma unroll
    for (int j = 0; j < 4; ++j) {
        dst[(tA * 128 + bA) * 4 + j] = make_float4(va[j], va[4+j], va[8+j], va[12+j]);
        dst[(tB * 128 + bB) * 4 + j] = make_float4(vb[j], vb[4+j], vb[8+j], vb[12+j]);
    }
}

// =====================================================================
// Kernel 2: forward LSTM, fused K-half combine. 8 blocks x 64 threads:
// warp0 = compute (16 batches, dual stream, 4 lanes/batch),
// warp1 = copy (cp.async, 16-step stages, both halves, double-buffered).
// (R5/R10 version, measured good.)
// =====================================================================
__global__ __launch_bounds__(64) void lstm_fwd_kernel(const float* __restrict__ Whh) {
    extern __shared__ float sx[];   // [buf][half][step][b][16] = 2*2*16*16*16 floats (64 KB)
    auto buf_at = [&](int p, int h, int tt, int b) -> float* {
        return sx + (((p * 2 + h) * 16 + tt) * 16 + b) * 16;
    };

    const int tid = threadIdx.x;
    const int blk_b0 = blockIdx.x * 16;

    if (tid >= 32) {
        // ---------------- copy warp ----------------
        const int l  = tid & 31;
        const int bb = l & 15;
        const int f0 = (l >> 4) * 8;
        auto fill = [&](int s) {
            const int t0 = s * 16;
            const int p = s & 1;
#pragma unroll
            for (int h = 0; h < 2; ++h) {
                const float* base = g_xph[h];
#pragma unroll
                for (int tt = 0; tt < 16; ++tt) {
                    const float* src = base + (((size_t)(t0 + tt) * 128) + blk_b0 + bb) * 16 + f0;
                    float* d = buf_at(p, h, tt, bb) + f0;
                    cp16(d, src);
                    cp16(d + 4, src + 4);
                }
            }
        };
        fill(0);
        asm volatile("cp.async.commit_group;");
        asm volatile("cp.async.wait_group 0;" ::: "memory");
        __syncthreads();
        for (int s = 0; s < 32; ++s) {
            if (s + 1 < 32) {
                fill(s + 1);
                asm volatile("cp.async.commit_group;");
                asm volatile("cp.async.wait_group 0;" ::: "memory");
            }
            __syncthreads();
        }
    } else {
        // ---------------- compute warp ----------------
        const int j  = tid & 3;
        const int pr = tid >> 2;
        const int bA = pr, bB = pr + 8;

        // 0.25 = 0.5(sigmoid fold) * 0.5(h2 fold); g-gate 0.5 (h2 fold only)
        float wi[4], wf[4], wg[4], wo[4];
#pragma unroll
        for (int k = 0; k < 4; ++k) {
            wi[k] = 0.25f * __ldg(&Whh[(0  + j) * 4 + k]);
            wf[k] = 0.25f * __ldg(&Whh[(4  + j) * 4 + k]);
            wg[k] = 0.50f * __ldg(&Whh[(8  + j) * 4 + k]);
            wo[k] = 0.25f * __ldg(&Whh[(12 + j) * 4 + k]);
        }

        float a0 = 0.f, a1 = 0.f, a2 = 0.f, a3 = 0.f, cA = 0.f, hA2 = 0.f;
        float e0 = 0.f, e1 = 0.f, e2 = 0.f, e3 = 0.f, cB = 0.f, hB2 = 0.f;

        __syncthreads();   // matches copy prologue sync

        for (int s = 0; s < 32; ++s) {
            const int p = s & 1;
            float4 cA0 = *reinterpret_cast<const float4*>(buf_at(p, 0, 0, bA) + 4 * j);
            float4 cA1 = *reinterpret_cast<const float4*>(buf_at(p, 1, 0, bA) + 4 * j);
            float4 cB0 = *reinterpret_cast<const float4*>(buf_at(p, 0, 0, bB) + 4 * j);
            float4 cB1 = *reinterpret_cast<const float4*>(buf_at(p, 1, 0, bB) + 4 * j);
#pragma unroll
            for (int tt = 0; tt < 16; ++tt) {
                float4 nA0, nA1, nB0, nB1;
                if (tt < 15) {
                    nA0 = *reinterpret_cast<const float4*>(buf_at(p, 0, tt + 1, bA) + 4 * j);
                    nA1 = *reinterpret_cast<const float4*>(buf_at(p, 1, tt + 1, bA) + 4 * j);
                    nB0 = *reinterpret_cast<const float4*>(buf_at(p, 0, tt + 1, bB) + 4 * j);
                    nB1 = *reinterpret_cast<const float4*>(buf_at(p, 1, tt + 1, bB) + 4 * j);
                }

                // balanced trees; half-1 partial folded into second tree
                float ipA = fmaf(wi[1], a1, fmaf(wi[0], a0, cA0.x)) + fmaf(wi[3], a3, fmaf(wi[2], a2, cA1.x));
                float fpA = fmaf(wf[1], a1, fmaf(wf[0], a0, cA0.y)) + fmaf(wf[3], a3, fmaf(wf[2], a2, cA1.y));
                float gpA = fmaf(wg[1], a1, fmaf(wg[0], a0, cA0.z)) + fmaf(wg[3], a3, fmaf(wg[2], a2, cA1.z));
                float opA = fmaf(wo[1], a1, fmaf(wo[0], a0, cA0.w)) + fmaf(wo[3], a3, fmaf(wo[2], a2, cA1.w));
                float ipB = fmaf(wi[1], e1, fmaf(wi[0], e0, cB0.x)) + fmaf(wi[3], e3, fmaf(wi[2], e2, cB1.x));
                float fpB = fmaf(wf[1], e1, fmaf(wf[0], e0, cB0.y)) + fmaf(wf[3], e3, fmaf(wf[2], e2, cB1.y));
                float gpB = fmaf(wg[1], e1, fmaf(wg[0], e0, cB0.z)) + fmaf(wg[3], e3, fmaf(wg[2], e2, cB1.z));
                float opB = fmaf(wo[1], e1, fmaf(wo[0], e0, cB0.w)) + fmaf(wo[3], e3, fmaf(wo[2], e2, cB1.w));

                const float tiA = tanha(ipA), tfA = tanha(fpA), tgA = tanha(gpA), toA = tanha(opA);
                const float tiB = tanha(ipB), tfB = tanha(fpB), tgB = tanha(gpB), toB = tanha(opB);

                cA = 0.5f * (fmaf(tfA, cA, cA) + fmaf(tiA, tgA, tgA));
                cB = 0.5f * (fmaf(tfB, cB, cB) + fmaf(tiB, tgB, tgB));

                const float tcA = tanha(cA);
                const float tcB = tanha(cB);
                hA2 = fmaf(toA, tcA, tcA);   // = 2*h
                hB2 = fmaf(toB, tcB, tcB);

                a0 = __shfl_sync(0xffffffffu, hA2, 0, 4);
                a1 = __shfl_sync(0xffffffffu, hA2, 1, 4);
                a2 = __shfl_sync(0xffffffffu, hA2, 2, 4);
                a3 = __shfl_sync(0xffffffffu, hA2, 3, 4);
                e0 = __shfl_sync(0xffffffffu, hB2, 0, 4);
                e1 = __shfl_sync(0xffffffffu, hB2, 1, 4);
                e2 = __shfl_sync(0xffffffffu, hB2, 2, 4);
                e3 = __shfl_sync(0xffffffffu, hB2, 3, 4);

                cA0 = nA0; cA1 = nA1; cB0 = nB0; cB1 = nB1;
            }
            __syncthreads();
        }

        g_hf[(blk_b0 + bA) * 4 + j] = 0.5f * hA2;
        g_hf[(blk_b0 + bB) * 4 + j] = 0.5f * hB2;
    }
}

// =====================================================================
// Kernel 3: tail. 128 blocks x 384 threads; warp w reduces one live gate
// row (i: 0-3, g: 8-11, o: 12-15). f-gate provably unused (c0 = 0).
// =====================================================================
__global__ __launch_bounds__(384) void tail_kernel(const float* __restrict__ x,
                                                   const float* __restrict__ Wihb,
                                                   const float* __restrict__ bihb,
                                                   const float* __restrict__ bhhb,
                                                   const float* __restrict__ Wout,
                                                   const float* __restrict__ bout,
                                                   float* __restrict__ out) {
    const int b = blockIdx.x;
    const int tid = threadIdx.x;
    const int w = tid >> 5;
    const int l = tid & 31;
    const int gr = (w < 4) ? w : (w + 4);    // gate row: 0-3, 8-11, 12-15

    __shared__ float sg[12];

    const float* xr = x + ((size_t)b * TSEQ + (TSEQ - 1)) * KIN;
    const float* wr = Wihb + (size_t)gr * KIN;

    float a = 0.f;
    for (int k = l; k < KIN; k += 32)
        a = fmaf(__ldg(&xr[k]), __ldg(&wr[k]), a);
#pragma unroll
    for (int s = 16; s > 0; s >>= 1)
        a += __shfl_xor_sync(0xffffffffu, a, s);
    if (l == 0) sg[w] = a + __ldg(&bihb[gr]) + __ldg(&bhhb[gr]);
    __syncthreads();

    if (tid == 0) {
        float hb[4], hf[4];
#pragma unroll
        for (int jj = 0; jj < 4; ++jj) {
            float iv = sigmoid_acc(sg[jj]);
            float gv = tanh_acc(sg[4 + jj]);
            float ov = sigmoid_acc(sg[8 + jj]);
            float cc = iv * gv;                 // c0 = 0 => f-gate drops out
            hb[jj] = ov * tanh_acc(cc);
            hf[jj] = g_hf[b * 4 + jj];
        }
#pragma unroll
        for (int o2 = 0; o2 < 2; ++o2) {
            float s = __ldg(&bout[o2]);
#pragma unroll
            for (int jj = 0; jj < 4; ++jj) {
                s = fmaf(__ldg(&Wout[o2 * 8 + jj]),     hf[jj], s);
                s = fmaf(__ldg(&Wout[o2 * 8 + 4 + jj]), hb[jj], s);
            }
            out[b * 2 + o2] = s;
        }
    }
}

// =====================================================================
extern "C" void kernel_launch(void* const* d_in, const int* in_sizes, int n_in,
                              void* d_out, int out_size) {
    const float* x    = (const float*)d_in[0];
    const float* Wihf = (const float*)d_in[1];
    const float* Whhf = (const float*)d_in[2];
    const float* bihf = (const float*)d_in[3];
    const float* bhhf = (const float*)d_in[4];
    const float* Wihb = (const float*)d_in[5];
    // d_in[6] = W_hh_b: provably unused (backward output only needs step 1 from zero state)
    const float* bihb = (const float*)d_in[7];
    const float* bhhb = (const float*)d_in[8];
    const float* Wout = (const float*)d_in[9];
    const float* bout = (const float*)d_in[10];
    float* out = (float*)d_out;

    constexpr int LSTM_SMEM = 2 * 2 * 16 * 16 * 16 * 4;   // 65536 B
    static bool attr_set = false;
    if (!attr_set) {
        cudaFuncSetAttribute(lstm_fwd_kernel, cudaFuncAttributeMaxDynamicSharedMemorySize, LSTM_SMEM);
        attr_set = true;
    }

    dim3 pgrid(BATCH * TSEQ / PROWS, 2);   // (256, 2)
    proj_kernel<<<pgrid, 128>>>(x, Wihf, bihf, bhhf);
    lstm_fwd_kernel<<<8, 64, LSTM_SMEM>>>(Whhf);
    tail_kernel<<<BATCH, 384>>>(x, Wihb, bihb, bhhb, Wout, bout, out);
}

// round 12
// speedup vs baseline: 1.0358x; 1.0358x over previous
#include <cuda_runtime.h>

// Problem constants
constexpr int BATCH = 128;
constexpr int TSEQ  = 512;
constexpr int KIN   = 906;
constexpr int NG    = 16;       // 4*H gates
constexpr int KHALF = 453;      // K split
constexpr int CK    = 8;        // k per chunk (small -> low staging regs)
constexpr int NCHK  = 57;       // 56*8 + 5
constexpr int PROWS = 256;      // rows per proj block
constexpr int PITCH = 260;      // k-major tile pitch: banks 4*kk+rs all distinct

// Scratch (device globals; no allocation allowed)
// K-half partials, layout [t][b][j][ifgo]; i/f/o pre-scaled 0.5 (sigmoid fold)
__device__ __align__(16) float g_xph[2][BATCH * TSEQ * NG];
__device__ float g_hf[BATCH * 4];

// ---------- packed fp32x2 helpers (Blackwell FFMA2) ----------
__device__ __forceinline__ unsigned long long pack2(float x) {
    unsigned long long r;
    asm("mov.b64 %0, {%1, %1};" : "=l"(r) : "f"(x));
    return r;
}
__device__ __forceinline__ unsigned long long fma2(unsigned long long a,
                                                   unsigned long long b,
                                                   unsigned long long c) {
    unsigned long long d;
    asm("fma.rn.f32x2 %0, %1, %2, %3;" : "=l"(d) : "l"(a), "l"(b), "l"(c));
    return d;
}
__device__ __forceinline__ void unpack2(unsigned long long a, float& lo, float& hi) {
    asm("mov.b64 {%0, %1}, %2;" : "=f"(lo), "=f"(hi) : "l"(a));
}

// ---------- activations ----------
__device__ __forceinline__ float tanha(float x) {
    float r;
    asm("tanh.approx.f32 %0, %1;" : "=f"(r) : "f"(x));
    return r;
}
__device__ __forceinline__ float sigmoid_acc(float x) {
    float e = __expf(-x);
    return __fdividef(1.0f, 1.0f + e);
}
__device__ __forceinline__ float tanh_acc(float x) {
    float e = __expf(2.0f * x);
    return 1.0f - __fdividef(2.0f, 1.0f + e);
}

// ---------- cp.async 16B (lstm feed) ----------
__device__ __forceinline__ void cp16(void* dst, const void* src) {
    unsigned d = (unsigned)__cvta_generic_to_shared(dst);
    asm volatile("cp.async.cg.shared.global [%0], [%1], 16;" :: "r"(d), "l"(src));
}

// =====================================================================
// Kernel 1: projection. grid (256, 2); 128 threads; R=2 rows/thread.
// R10 structure (static depth-2 register staging, LDG->STS) with CK=8
// so staging banks are 16 regs -> total ~100 regs -> 5 blocks/SM ->
// all 512 blocks resident in ONE wave.
// =====================================================================
__global__ __launch_bounds__(128, 5) void proj_kernel(const float* __restrict__ x,
                                                      const float* __restrict__ Wih,
                                                      const float* __restrict__ bih,
                                                      const float* __restrict__ bhh) {
    __shared__ __align__(16) float sxT[2][CK * PITCH];  // [buf][k][row]  ~16.6 KB
    __shared__ __align__(16) float sw[2][CK * 16];      // [buf][k][gate]  1 KB

    const int tid  = threadIdx.x;
    const int lane = tid & 31;
    const int wid  = tid >> 5;
    const int half = blockIdx.y;
    const int kb   = half * KHALF;
    const size_t row0 = (size_t)blockIdx.x * PROWS;

    const int kk_l = lane & 7;      // k within chunk
    const int rs   = lane >> 3;     // row sub (0..3)
    const int wkw  = tid >> 4;      // W k (0..7)
    const int wg   = tid & 15;      // W gate
    const float wsc = ((wg >> 2) == 2) ? 1.0f : 0.5f;   // g-type unscaled

    unsigned long long accA[8], accB[8];
#pragma unroll
    for (int m = 0; m < 8; ++m) { accA[m] = 0ull; accB[m] = 0ull; }

    float xr0[16], xr1[16];   // STATIC depth-2 banks (16 regs each)
    float wr0, wr1;

    // coalesced LDG of chunk ch into the given bank
    auto ldg_chunk = [&](int ch, float (&xr)[16], float& wr) {
        const int kloc = ch * CK + kk_l;
        const bool ok = kloc < KHALF;
        const float* xp = x + (row0 + 64 * wid + rs) * KIN + kb + kloc;
#pragma unroll
        for (int i = 0; i < 16; ++i)
            xr[i] = ok ? __ldg(xp + (size_t)4 * i * KIN) : 0.0f;
        const int kwl = ch * CK + wkw;
        wr = (kwl < KHALF) ? wsc * __ldg(Wih + (size_t)wg * KIN + kb + kwl) : 0.0f;
    };
    auto sts_chunk = [&](const float (&xr)[16], const float wr, int buf) {
        float* sx = sxT[buf];
#pragma unroll
        for (int i = 0; i < 16; ++i)
            sx[kk_l * PITCH + 64 * wid + rs + 4 * i] = xr[i];
        sw[buf][tid] = wr;                   // [k][g]: tid = kw*16+g
    };

#define PROJ_K(SX, SW, KK)                                                     \
    {                                                                          \
        const float2 xv = *(const float2*)((SX) + (KK) * PITCH + 2 * tid);     \
        const unsigned long long xa = pack2(xv.x);                             \
        const unsigned long long xb = pack2(xv.y);                             \
        const ulonglong2* wr = (const ulonglong2*)((SW) + (KK) * 16);          \
        ulonglong2 w0 = wr[0], w1 = wr[1];                                     \
        accA[0] = fma2(xa, w0.x, accA[0]);  accB[0] = fma2(xb, w0.x, accB[0]); \
        accA[1] = fma2(xa, w0.y, accA[1]);  accB[1] = fma2(xb, w0.y, accB[1]); \
        accA[2] = fma2(xa, w1.x, accA[2]);  accB[2] = fma2(xb, w1.x, accB[2]); \
        accA[3] = fma2(xa, w1.y, accA[3]);  accB[3] = fma2(xb, w1.y, accB[3]); \
        ulonglong2 w2 = wr[2], w3 = wr[3];                                     \
        accA[4] = fma2(xa, w2.x, accA[4]);  accB[4] = fma2(xb, w2.x, accB[4]); \
        accA[5] = fma2(xa, w2.y, accA[5]);  accB[5] = fma2(xb, w2.y, accB[5]); \
        accA[6] = fma2(xa, w3.x, accA[6]);  accB[6] = fma2(xb, w3.x, accB[6]); \
        accA[7] = fma2(xa, w3.y, accA[7]);  accB[7] = fma2(xb, w3.y, accB[7]); \
    }

    // depth-2 prologue: banks hold chunks 0,1; chunk 0 staged to smem buf0
    ldg_chunk(0, xr0, wr0);
    ldg_chunk(1, xr1, wr1);
    sts_chunk(xr0, wr0, 0);
    __syncthreads();

    // 28 even/odd pairs cover chunks 0..55; chunk 56 handled after.
#pragma unroll 1
    for (int c2 = 0; c2 < 28; ++c2) {
        const int ch = 2 * c2;
        // ---- even body: consumes buf0 (chunk ch), bank0 free -> load ch+2
        ldg_chunk(ch + 2, xr0, wr0);
        {
            const float* sx = sxT[0];
            const float* swp = sw[0];
#pragma unroll
            for (int kk = 0; kk < CK; ++kk) PROJ_K(sx, swp, kk)
        }
        sts_chunk(xr1, wr1, 1);          // stage chunk ch+1 into buf1
        __syncthreads();
        // ---- odd body: consumes buf1 (chunk ch+1), bank1 free -> load ch+3
        if (ch + 3 < NCHK) ldg_chunk(ch + 3, xr1, wr1);
        {
            const float* sx = sxT[1];
            const float* swp = sw[1];
#pragma unroll
            for (int kk = 0; kk < CK; ++kk) PROJ_K(sx, swp, kk)
        }
        sts_chunk(xr0, wr0, 0);          // stage chunk ch+2 into buf0
        __syncthreads();
    }
    // ---- final chunk 56 (5 valid k) in buf0
    {
        const float* sx = sxT[0];
        const float* swp = sw[0];
#pragma unroll
        for (int kk = 0; kk < KHALF - CK * (NCHK - 1); ++kk) PROJ_K(sx, swp, kk)
    }
#undef PROJ_K

    // epilogue: unpack, bias (half 0, scaled), store [t][b][j][ifgo]
    float va[16], vb[16];
#pragma unroll
    for (int m = 0; m < 8; ++m) { unpack2(accA[m], va[2*m], va[2*m+1]);
                                  unpack2(accB[m], vb[2*m], vb[2*m+1]); }
    if (half == 0) {
#pragma unroll
        for (int g = 0; g < 16; ++g) {
            const float sc = (g >= 8 && g < 12) ? 1.0f : 0.5f;
            const float b = sc * (__ldg(&bih[g]) + __ldg(&bhh[g]));
            va[g] += b; vb[g] += b;
        }
    }

    float4* dst = reinterpret_cast<float4*>(g_xph[half]);
    const size_t rA = row0 + 2 * tid;
    const size_t tA = rA & 511, bA = rA >> 9;
    const size_t tB = (rA + 1) & 511, bB = (rA + 1) >> 9;
#pragma unroll
    for (int j = 0; j < 4; ++j) {
        dst[(tA * 128 + bA) * 4 + j] = make_float4(va[j], va[4+j], va[8+j], va[12+j]);
        dst[(tB * 128 + bB) * 4 + j] = make_float4(vb[j], vb[4+j], vb[8+j], vb[12+j]);
    }
}

// =====================================================================
// Kernel 2: forward LSTM, fused K-half combine. 8 blocks x 64 threads:
// warp0 = compute (16 batches, dual stream, 4 lanes/batch),
// warp1 = copy (cp.async, 16-step stages, both halves, double-buffered).
// (R5/R10 version, measured good.)
// =====================================================================
__global__ __launch_bounds__(64) void lstm_fwd_kernel(const float* __restrict__ Whh) {
    extern __shared__ float sx[];   // [buf][half][step][b][16] = 2*2*16*16*16 floats (64 KB)
    auto buf_at = [&](int p, int h, int tt, int b) -> float* {
        return sx + (((p * 2 + h) * 16 + tt) * 16 + b) * 16;
    };

    const int tid = threadIdx.x;
    const int blk_b0 = blockIdx.x * 16;

    if (tid >= 32) {
        // ---------------- copy warp ----------------
        const int l  = tid & 31;
        const int bb = l & 15;
        const int f0 = (l >> 4) * 8;
        auto fill = [&](int s) {
            const int t0 = s * 16;
            const int p = s & 1;
#pragma unroll
            for (int h = 0; h < 2; ++h) {
                const float* base = g_xph[h];
#pragma unroll
                for (int tt = 0; tt < 16; ++tt) {
                    const float* src = base + (((size_t)(t0 + tt) * 128) + blk_b0 + bb) * 16 + f0;
                    float* d = buf_at(p, h, tt, bb) + f0;
                    cp16(d, src);
                    cp16(d + 4, src + 4);
                }
            }
        };
        fill(0);
        asm volatile("cp.async.commit_group;");
        asm volatile("cp.async.wait_group 0;" ::: "memory");
        __syncthreads();
        for (int s = 0; s < 32; ++s) {
            if (s + 1 < 32) {
                fill(s + 1);
                asm volatile("cp.async.commit_group;");
                asm volatile("cp.async.wait_group 0;" ::: "memory");
            }
            __syncthreads();
        }
    } else {
        // ---------------- compute warp ----------------
        const int j  = tid & 3;
        const int pr = tid >> 2;
        const int bA = pr, bB = pr + 8;

        // 0.25 = 0.5(sigmoid fold) * 0.5(h2 fold); g-gate 0.5 (h2 fold only)
        float wi[4], wf[4], wg[4], wo[4];
#pragma unroll
        for (int k = 0; k < 4; ++k) {
            wi[k] = 0.25f * __ldg(&Whh[(0  + j) * 4 + k]);
            wf[k] = 0.25f * __ldg(&Whh[(4  + j) * 4 + k]);
            wg[k] = 0.50f * __ldg(&Whh[(8  + j) * 4 + k]);
            wo[k] = 0.25f * __ldg(&Whh[(12 + j) * 4 + k]);
        }

        float a0 = 0.f, a1 = 0.f, a2 = 0.f, a3 = 0.f, cA = 0.f, hA2 = 0.f;
        float e0 = 0.f, e1 = 0.f, e2 = 0.f, e3 = 0.f, cB = 0.f, hB2 = 0.f;

        __syncthreads();   // matches copy prologue sync

        for (int s = 0; s < 32; ++s) {
            const int p = s & 1;
            float4 cA0 = *reinterpret_cast<const float4*>(buf_at(p, 0, 0, bA) + 4 * j);
            float4 cA1 = *reinterpret_cast<const float4*>(buf_at(p, 1, 0, bA) + 4 * j);
            float4 cB0 = *reinterpret_cast<const float4*>(buf_at(p, 0, 0, bB) + 4 * j);
            float4 cB1 = *reinterpret_cast<const float4*>(buf_at(p, 1, 0, bB) + 4 * j);
#pragma unroll
            for (int tt = 0; tt < 16; ++tt) {
                float4 nA0, nA1, nB0, nB1;
                if (tt < 15) {
                    nA0 = *reinterpret_cast<const float4*>(buf_at(p, 0, tt + 1, bA) + 4 * j);
                    nA1 = *reinterpret_cast<const float4*>(buf_at(p, 1, tt + 1, bA) + 4 * j);
                    nB0 = *reinterpret_cast<const float4*>(buf_at(p, 0, tt + 1, bB) + 4 * j);
                    nB1 = *reinterpret_cast<const float4*>(buf_at(p, 1, tt + 1, bB) + 4 * j);
                }

                // balanced trees; half-1 partial folded into second tree
                float ipA = fmaf(wi[1], a1, fmaf(wi[0], a0, cA0.x)) + fmaf(wi[3], a3, fmaf(wi[2], a2, cA1.x));
                float fpA = fmaf(wf[1], a1, fmaf(wf[0], a0, cA0.y)) + fmaf(wf[3], a3, fmaf(wf[2], a2, cA1.y));
                float gpA = fmaf(wg[1], a1, fmaf(wg[0], a0, cA0.z)) + fmaf(wg[3], a3, fmaf(wg[2], a2, cA1.z));
                float opA = fmaf(wo[1], a1, fmaf(wo[0], a0, cA0.w)) + fmaf(wo[3], a3, fmaf(wo[2], a2, cA1.w));
                float ipB = fmaf(wi[1], e1, fmaf(wi[0], e0, cB0.x)) + fmaf(wi[3], e3, fmaf(wi[2], e2, cB1.x));
                float fpB = fmaf(wf[1], e1, fmaf(wf[0], e0, cB0.y)) + fmaf(wf[3], e3, fmaf(wf[2], e2, cB1.y));
                float gpB = fmaf(wg[1], e1, fmaf(wg[0], e0, cB0.z)) + fmaf(wg[3], e3, fmaf(wg[2], e2, cB1.z));
                float opB = fmaf(wo[1], e1, fmaf(wo[0], e0, cB0.w)) + fmaf(wo[3], e3, fmaf(wo[2], e2, cB1.w));

                const float tiA = tanha(ipA), tfA = tanha(fpA), tgA = tanha(gpA), toA = tanha(opA);
                const float tiB = tanha(ipB), tfB = tanha(fpB), tgB = tanha(gpB), toB = tanha(opB);

                cA = 0.5f * (fmaf(tfA, cA, cA) + fmaf(tiA, tgA, tgA));
                cB = 0.5f * (fmaf(tfB, cB, cB) + fmaf(tiB, tgB, tgB));

                const float tcA = tanha(cA);
                const float tcB = tanha(cB);
                hA2 = fmaf(toA, tcA, tcA);   // = 2*h
                hB2 = fmaf(toB, tcB, tcB);

                a0 = __shfl_sync(0xffffffffu, hA2, 0, 4);
                a1 = __shfl_sync(0xffffffffu, hA2, 1, 4);
                a2 = __shfl_sync(0xffffffffu, hA2, 2, 4);
                a3 = __shfl_sync(0xffffffffu, hA2, 3, 4);
                e0 = __shfl_sync(0xffffffffu, hB2, 0, 4);
                e1 = __shfl_sync(0xffffffffu, hB2, 1, 4);
                e2 = __shfl_sync(0xffffffffu, hB2, 2, 4);
                e3 = __shfl_sync(0xffffffffu, hB2, 3, 4);

                cA0 = nA0; cA1 = nA1; cB0 = nB0; cB1 = nB1;
            }
            __syncthreads();
        }

        g_hf[(blk_b0 + bA) * 4 + j] = 0.5f * hA2;
        g_hf[(blk_b0 + bB) * 4 + j] = 0.5f * hB2;
    }
}

// =====================================================================
// Kernel 3: tail. 128 blocks x 384 threads; warp w reduces one live gate
// row (i: 0-3, g: 8-11, o: 12-15). f-gate provably unused (c0 = 0).
// =====================================================================
__global__ __launch_bounds__(384) void tail_kernel(const float* __restrict__ x,
                                                   const float* __restrict__ Wihb,
                                                   const float* __restrict__ bihb,
                                                   const float* __restrict__ bhhb,
                                                   const float* __restrict__ Wout,
                                                   const float* __restrict__ bout,
                                                   float* __restrict__ out) {
    const int b = blockIdx.x;
    const int tid = threadIdx.x;
    const int w = tid >> 5;
    const int l = tid & 31;
    const int gr = (w < 4) ? w : (w + 4);    // gate row: 0-3, 8-11, 12-15

    __shared__ float sg[12];

    const float* xr = x + ((size_t)b * TSEQ + (TSEQ - 1)) * KIN;
    const float* wr = Wihb + (size_t)gr * KIN;

    float a = 0.f;
    for (int k = l; k < KIN; k += 32)
        a = fmaf(__ldg(&xr[k]), __ldg(&wr[k]), a);
#pragma unroll
    for (int s = 16; s > 0; s >>= 1)
        a += __shfl_xor_sync(0xffffffffu, a, s);
    if (l == 0) sg[w] = a + __ldg(&bihb[gr]) + __ldg(&bhhb[gr]);
    __syncthreads();

    if (tid == 0) {
        float hb[4], hf[4];
#pragma unroll
        for (int jj = 0; jj < 4; ++jj) {
            float iv = sigmoid_acc(sg[jj]);
            float gv = tanh_acc(sg[4 + jj]);
            float ov = sigmoid_acc(sg[8 + jj]);
            float cc = iv * gv;                 // c0 = 0 => f-gate drops out
            hb[jj] = ov * tanh_acc(cc);
            hf[jj] = g_hf[b * 4 + jj];
        }
#pragma unroll
        for (int o2 = 0; o2 < 2; ++o2) {
            float s = __ldg(&bout[o2]);
#pragma unroll
            for (int jj = 0; jj < 4; ++jj) {
                s = fmaf(__ldg(&Wout[o2 * 8 + jj]),     hf[jj], s);
                s = fmaf(__ldg(&Wout[o2 * 8 + 4 + jj]), hb[jj], s);
            }
            out[b * 2 + o2] = s;
        }
    }
}

// =====================================================================
extern "C" void kernel_launch(void* const* d_in, const int* in_sizes, int n_in,
                              void* d_out, int out_size) {
    const float* x    = (const float*)d_in[0];
    const float* Wihf = (const float*)d_in[1];
    const float* Whhf = (const float*)d_in[2];
    const float* bihf = (const float*)d_in[3];
    const float* bhhf = (const float*)d_in[4];
    const float* Wihb = (const float*)d_in[5];
    // d_in[6] = W_hh_b: provably unused (backward output only needs step 1 from zero state)
    const float* bihb = (const float*)d_in[7];
    const float* bhhb = (const float*)d_in[8];
    const float* Wout = (const float*)d_in[9];
    const float* bout = (const float*)d_in[10];
    float* out = (float*)d_out;

    constexpr int LSTM_SMEM = 2 * 2 * 16 * 16 * 16 * 4;   // 65536 B
    static bool attr_set = false;
    if (!attr_set) {
        cudaFuncSetAttribute(lstm_fwd_kernel, cudaFuncAttributeMaxDynamicSharedMemorySize, LSTM_SMEM);
        attr_set = true;
    }

    dim3 pgrid(BATCH * TSEQ / PROWS, 2);   // (256, 2)
    proj_kernel<<<pgrid, 128>>>(x, Wihf, bihf, bhhf);
    lstm_fwd_kernel<<<8, 64, LSTM_SMEM>>>(Whhf);
    tail_kernel<<<BATCH, 384>>>(x, Wihb, bihb, bhhb, Wout, bout, out);
}

// round 13
// speedup vs baseline: 1.0795x; 1.0422x over previous
#include <cuda_runtime.h>

// Problem constants
constexpr int BATCH = 128;
constexpr int TSEQ  = 512;
constexpr int KIN   = 906;
constexpr int NG    = 16;       // 4*H gates
constexpr int KHALF = 453;      // K split
constexpr int CK    = 8;        // k per chunk
constexpr int NCHK  = 57;       // 56*8 + 5
constexpr int PROWS = 512;      // rows per proj block (= one batch)
constexpr int PITCH = 516;      // k-major tile pitch (mult of 4 -> LDS.128 aligned; 516%32=4 -> STS conflict-free)

// Scratch (device globals; no allocation allowed)
// K-half partials, layout [t][b][j][ifgo]; i/f/o pre-scaled 0.5 (sigmoid fold)
__device__ __align__(16) float g_xph[2][BATCH * TSEQ * NG];
__device__ float g_hf[BATCH * 4];

// ---------- packed fp32x2 helpers (Blackwell FFMA2) ----------
__device__ __forceinline__ unsigned long long pack2(float x) {
    unsigned long long r;
    asm("mov.b64 %0, {%1, %1};" : "=l"(r) : "f"(x));
    return r;
}
__device__ __forceinline__ unsigned long long fma2(unsigned long long a,
                                                   unsigned long long b,
                                                   unsigned long long c) {
    unsigned long long d;
    asm("fma.rn.f32x2 %0, %1, %2, %3;" : "=l"(d) : "l"(a), "l"(b), "l"(c));
    return d;
}
__device__ __forceinline__ void unpack2(unsigned long long a, float& lo, float& hi) {
    asm("mov.b64 {%0, %1}, %2;" : "=f"(lo), "=f"(hi) : "l"(a));
}

// ---------- activations ----------
__device__ __forceinline__ float tanha(float x) {
    float r;
    asm("tanh.approx.f32 %0, %1;" : "=f"(r) : "f"(x));
    return r;
}
__device__ __forceinline__ float sigmoid_acc(float x) {
    float e = __expf(-x);
    return __fdividef(1.0f, 1.0f + e);
}
__device__ __forceinline__ float tanh_acc(float x) {
    float e = __expf(2.0f * x);
    return 1.0f - __fdividef(2.0f, 1.0f + e);
}

// ---------- cp.async 16B (lstm feed) ----------
__device__ __forceinline__ void cp16(void* dst, const void* src) {
    unsigned d = (unsigned)__cvta_generic_to_shared(dst);
    asm volatile("cp.async.cg.shared.global [%0], [%1], 16;" :: "r"(d), "l"(src));
}

// =====================================================================
// Kernel 1: projection. grid (128, 2); 128 threads; R=4 rows/thread.
// One batch per block (rows = t 0..511). Compute reads x via ONE
// LDS.128 per k (4 rows), W via 4 broadcast LDS.128 -> 5 LDS per
// 32 FFMA2 (halved L1-per-FLOP vs R12). Depth-2 static register
// staging; launch_bounds(128,2) -> 256 regs avail, single wave.
// =====================================================================
__global__ __launch_bounds__(128, 2) void proj_kernel(const float* __restrict__ x,
                                                      const float* __restrict__ Wih,
                                                      const float* __restrict__ bih,
                                                      const float* __restrict__ bhh) {
    __shared__ __align__(16) float sxT[2][CK * PITCH];  // [buf][k][row]  ~33 KB
    __shared__ __align__(16) float sw[2][CK * 16];      // [buf][k][gate]  1 KB

    const int tid  = threadIdx.x;
    const int lane = tid & 31;
    const int wid  = tid >> 5;
    const int half = blockIdx.y;
    const int kb   = half * KHALF;
    const size_t row0 = (size_t)blockIdx.x * PROWS;     // = batch * 512

    const int kk_l = lane & 7;      // k within chunk (staging)
    const int rs   = lane >> 3;     // row sub (0..3)  (staging)
    const int wkw  = tid >> 4;      // W k (0..7)
    const int wg   = tid & 15;      // W gate
    const float wsc = ((wg >> 2) == 2) ? 1.0f : 0.5f;   // g-type unscaled

    unsigned long long acc[4][8];   // [row r][gate-pair]
#pragma unroll
    for (int r = 0; r < 4; ++r)
#pragma unroll
        for (int m = 0; m < 8; ++m) acc[r][m] = 0ull;

    float xr0[32], xr1[32];   // STATIC depth-2 staging banks
    float wr0, wr1;

    // coalesced LDG of chunk ch into the given bank
    // thread covers rows 128*wid + rs + 4*i, i=0..31
    auto ldg_chunk = [&](int ch, float (&xr)[32], float& wr) {
        const int kloc = ch * CK + kk_l;
        const bool ok = kloc < KHALF;
        const float* xp = x + (row0 + 128 * wid + rs) * KIN + kb + kloc;
#pragma unroll
        for (int i = 0; i < 32; ++i)
            xr[i] = ok ? __ldg(xp + (size_t)4 * i * KIN) : 0.0f;
        const int kwl = ch * CK + wkw;
        wr = (kwl < KHALF) ? wsc * __ldg(Wih + (size_t)wg * KIN + kb + kwl) : 0.0f;
    };
    auto sts_chunk = [&](const float (&xr)[32], const float wr, int buf) {
        float* sx = sxT[buf];
#pragma unroll
        for (int i = 0; i < 32; ++i)
            sx[kk_l * PITCH + 128 * wid + rs + 4 * i] = xr[i];
        sw[buf][tid] = wr;                   // [k][g]: tid = kw*16+g
    };

#define PROJ_K(SX, SW, KK)                                                     \
    {                                                                          \
        const float4 xq = *(const float4*)((SX) + (KK) * PITCH + 4 * tid);     \
        const unsigned long long x0 = pack2(xq.x);                             \
        const unsigned long long x1 = pack2(xq.y);                             \
        const unsigned long long x2 = pack2(xq.z);                             \
        const unsigned long long x3 = pack2(xq.w);                             \
        const ulonglong2* wr = (const ulonglong2*)((SW) + (KK) * 16);          \
        ulonglong2 w0 = wr[0], w1 = wr[1];                                     \
        acc[0][0] = fma2(x0, w0.x, acc[0][0]);                                 \
        acc[0][1] = fma2(x0, w0.y, acc[0][1]);                                 \
        acc[0][2] = fma2(x0, w1.x, acc[0][2]);                                 \
        acc[0][3] = fma2(x0, w1.y, acc[0][3]);                                 \
        acc[1][0] = fma2(x1, w0.x, acc[1][0]);                                 \
        acc[1][1] = fma2(x1, w0.y, acc[1][1]);                                 \
        acc[1][2] = fma2(x1, w1.x, acc[1][2]);                                 \
        acc[1][3] = fma2(x1, w1.y, acc[1][3]);                                 \
        acc[2][0] = fma2(x2, w0.x, acc[2][0]);                                 \
        acc[2][1] = fma2(x2, w0.y, acc[2][1]);                                 \
        acc[2][2] = fma2(x2, w1.x, acc[2][2]);                                 \
        acc[2][3] = fma2(x2, w1.y, acc[2][3]);                                 \
        acc[3][0] = fma2(x3, w0.x, acc[3][0]);                                 \
        acc[3][1] = fma2(x3, w0.y, acc[3][1]);                                 \
        acc[3][2] = fma2(x3, w1.x, acc[3][2]);                                 \
        acc[3][3] = fma2(x3, w1.y, acc[3][3]);                                 \
        ulonglong2 w2 = wr[2], w3 = wr[3];                                     \
        acc[0][4] = fma2(x0, w2.x, acc[0][4]);                                 \
        acc[0][5] = fma2(x0, w2.y, acc[0][5]);                                 \
        acc[0][6] = fma2(x0, w3.x, acc[0][6]);                                 \
        acc[0][7] = fma2(x0, w3.y, acc[0][7]);                                 \
        acc[1][4] = fma2(x1, w2.x, acc[1][4]);                                 \
        acc[1][5] = fma2(x1, w2.y, acc[1][5]);                                 \
        acc[1][6] = fma2(x1, w3.x, acc[1][6]);                                 \
        acc[1][7] = fma2(x1, w3.y, acc[1][7]);                                 \
        acc[2][4] = fma2(x2, w2.x, acc[2][4]);                                 \
        acc[2][5] = fma2(x2, w2.y, acc[2][5]);                                 \
        acc[2][6] = fma2(x2, w3.x, acc[2][6]);                                 \
        acc[2][7] = fma2(x2, w3.y, acc[2][7]);                                 \
        acc[3][4] = fma2(x3, w2.x, acc[3][4]);                                 \
        acc[3][5] = fma2(x3, w2.y, acc[3][5]);                                 \
        acc[3][6] = fma2(x3, w3.x, acc[3][6]);                                 \
        acc[3][7] = fma2(x3, w3.y, acc[3][7]);                                 \
    }

    // depth-2 prologue: banks hold chunks 0,1; chunk 0 staged to smem buf0
    ldg_chunk(0, xr0, wr0);
    ldg_chunk(1, xr1, wr1);
    sts_chunk(xr0, wr0, 0);
    __syncthreads();

    // 28 even/odd pairs cover chunks 0..55; chunk 56 handled after.
#pragma unroll 1
    for (int c2 = 0; c2 < 28; ++c2) {
        const int ch = 2 * c2;
        // ---- even body: consumes buf0 (chunk ch), bank0 free -> load ch+2
        ldg_chunk(ch + 2, xr0, wr0);
        {
            const float* sx = sxT[0];
            const float* swp = sw[0];
#pragma unroll
            for (int kk = 0; kk < CK; ++kk) PROJ_K(sx, swp, kk)
        }
        sts_chunk(xr1, wr1, 1);          // stage chunk ch+1 into buf1
        __syncthreads();
        // ---- odd body: consumes buf1 (chunk ch+1), bank1 free -> load ch+3
        if (ch + 3 < NCHK) ldg_chunk(ch + 3, xr1, wr1);
        {
            const float* sx = sxT[1];
            const float* swp = sw[1];
#pragma unroll
            for (int kk = 0; kk < CK; ++kk) PROJ_K(sx, swp, kk)
        }
        sts_chunk(xr0, wr0, 0);          // stage chunk ch+2 into buf0
        __syncthreads();
    }
    // ---- final chunk 56 (5 valid k) in buf0
    {
        const float* sx = sxT[0];
        const float* swp = sw[0];
#pragma unroll
        for (int kk = 0; kk < KHALF - CK * (NCHK - 1); ++kk) PROJ_K(sx, swp, kk)
    }
#undef PROJ_K

    // epilogue: unpack, bias (half 0, scaled), store [t][b][j][ifgo]
    // this thread's rows: row = 4*tid + r  (t = row, b = blockIdx.x)
    float* dst = g_xph[half];
    const size_t bidx = blockIdx.x;
#pragma unroll
    for (int r = 0; r < 4; ++r) {
        float v[16];
#pragma unroll
        for (int m = 0; m < 8; ++m) unpack2(acc[r][m], v[2 * m], v[2 * m + 1]);
        if (half == 0) {
#pragma unroll
            for (int g = 0; g < 16; ++g) {
                const float sc = (g >= 8 && g < 12) ? 1.0f : 0.5f;
                v[g] += sc * (__ldg(&bih[g]) + __ldg(&bhh[g]));
            }
        }
        const size_t t = 4 * (size_t)tid + r;
        float4* d4 = reinterpret_cast<float4*>(dst + (t * 128 + bidx) * NG);
#pragma unroll
        for (int j = 0; j < 4; ++j)
            d4[j] = make_float4(v[j], v[4 + j], v[8 + j], v[12 + j]);
    }
}

// =====================================================================
// Kernel 2: forward LSTM, fused K-half combine. 8 blocks x 64 threads:
// warp0 = compute (16 batches, dual stream, 4 lanes/batch),
// warp1 = copy (cp.async, 16-step stages, both halves, double-buffered).
// (R5/R10 version, measured good.)
// =====================================================================
__global__ __launch_bounds__(64) void lstm_fwd_kernel(const float* __restrict__ Whh) {
    extern __shared__ float sx[];   // [buf][half][step][b][16] = 2*2*16*16*16 floats (64 KB)
    auto buf_at = [&](int p, int h, int tt, int b) -> float* {
        return sx + (((p * 2 + h) * 16 + tt) * 16 + b) * 16;
    };

    const int tid = threadIdx.x;
    const int blk_b0 = blockIdx.x * 16;

    if (tid >= 32) {
        // ---------------- copy warp ----------------
        const int l  = tid & 31;
        const int bb = l & 15;
        const int f0 = (l >> 4) * 8;
        auto fill = [&](int s) {
            const int t0 = s * 16;
            const int p = s & 1;
#pragma unroll
            for (int h = 0; h < 2; ++h) {
                const float* base = g_xph[h];
#pragma unroll
                for (int tt = 0; tt < 16; ++tt) {
                    const float* src = base + (((size_t)(t0 + tt) * 128) + blk_b0 + bb) * 16 + f0;
                    float* d = buf_at(p, h, tt, bb) + f0;
                    cp16(d, src);
                    cp16(d + 4, src + 4);
                }
            }
        };
        fill(0);
        asm volatile("cp.async.commit_group;");
        asm volatile("cp.async.wait_group 0;" ::: "memory");
        __syncthreads();
        for (int s = 0; s < 32; ++s) {
            if (s + 1 < 32) {
                fill(s + 1);
                asm volatile("cp.async.commit_group;");
                asm volatile("cp.async.wait_group 0;" ::: "memory");
            }
            __syncthreads();
        }
    } else {
        // ---------------- compute warp ----------------
        const int j  = tid & 3;
        const int pr = tid >> 2;
        const int bA = pr, bB = pr + 8;

        // 0.25 = 0.5(sigmoid fold) * 0.5(h2 fold); g-gate 0.5 (h2 fold only)
        float wi[4], wf[4], wg[4], wo[4];
#pragma unroll
        for (int k = 0; k < 4; ++k) {
            wi[k] = 0.25f * __ldg(&Whh[(0  + j) * 4 + k]);
            wf[k] = 0.25f * __ldg(&Whh[(4  + j) * 4 + k]);
            wg[k] = 0.50f * __ldg(&Whh[(8  + j) * 4 + k]);
            wo[k] = 0.25f * __ldg(&Whh[(12 + j) * 4 + k]);
        }

        float a0 = 0.f, a1 = 0.f, a2 = 0.f, a3 = 0.f, cA = 0.f, hA2 = 0.f;
        float e0 = 0.f, e1 = 0.f, e2 = 0.f, e3 = 0.f, cB = 0.f, hB2 = 0.f;

        __syncthreads();   // matches copy prologue sync

        for (int s = 0; s < 32; ++s) {
            const int p = s & 1;
            float4 cA0 = *reinterpret_cast<const float4*>(buf_at(p, 0, 0, bA) + 4 * j);
            float4 cA1 = *reinterpret_cast<const float4*>(buf_at(p, 1, 0, bA) + 4 * j);
            float4 cB0 = *reinterpret_cast<const float4*>(buf_at(p, 0, 0, bB) + 4 * j);
            float4 cB1 = *reinterpret_cast<const float4*>(buf_at(p, 1, 0, bB) + 4 * j);
#pragma unroll
            for (int tt = 0; tt < 16; ++tt) {
                float4 nA0, nA1, nB0, nB1;
                if (tt < 15) {
                    nA0 = *reinterpret_cast<const float4*>(buf_at(p, 0, tt + 1, bA) + 4 * j);
                    nA1 = *reinterpret_cast<const float4*>(buf_at(p, 1, tt + 1, bA) + 4 * j);
                    nB0 = *reinterpret_cast<const float4*>(buf_at(p, 0, tt + 1, bB) + 4 * j);
                    nB1 = *reinterpret_cast<const float4*>(buf_at(p, 1, tt + 1, bB) + 4 * j);
                }

                // balanced trees; half-1 partial folded into second tree
                float ipA = fmaf(wi[1], a1, fmaf(wi[0], a0, cA0.x)) + fmaf(wi[3], a3, fmaf(wi[2], a2, cA1.x));
                float fpA = fmaf(wf[1], a1, fmaf(wf[0], a0, cA0.y)) + fmaf(wf[3], a3, fmaf(wf[2], a2, cA1.y));
                float gpA = fmaf(wg[1], a1, fmaf(wg[0], a0, cA0.z)) + fmaf(wg[3], a3, fmaf(wg[2], a2, cA1.z));
                float opA = fmaf(wo[1], a1, fmaf(wo[0], a0, cA0.w)) + fmaf(wo[3], a3, fmaf(wo[2], a2, cA1.w));
                float ipB = fmaf(wi[1], e1, fmaf(wi[0], e0, cB0.x)) + fmaf(wi[3], e3, fmaf(wi[2], e2, cB1.x));
                float fpB = fmaf(wf[1], e1, fmaf(wf[0], e0, cB0.y)) + fmaf(wf[3], e3, fmaf(wf[2], e2, cB1.y));
                float gpB = fmaf(wg[1], e1, fmaf(wg[0], e0, cB0.z)) + fmaf(wg[3], e3, fmaf(wg[2], e2, cB1.z));
                float opB = fmaf(wo[1], e1, fmaf(wo[0], e0, cB0.w)) + fmaf(wo[3], e3, fmaf(wo[2], e2, cB1.w));

                const float tiA = tanha(ipA), tfA = tanha(fpA), tgA = tanha(gpA), toA = tanha(opA);
                const float tiB = tanha(ipB), tfB = tanha(fpB), tgB = tanha(gpB), toB = tanha(opB);

                cA = 0.5f * (fmaf(tfA, cA, cA) + fmaf(tiA, tgA, tgA));
                cB = 0.5f * (fmaf(tfB, cB, cB) + fmaf(tiB, tgB, tgB));

                const float tcA = tanha(cA);
                const float tcB = tanha(cB);
                hA2 = fmaf(toA, tcA, tcA);   // = 2*h
                hB2 = fmaf(toB, tcB, tcB);

                a0 = __shfl_sync(0xffffffffu, hA2, 0, 4);
                a1 = __shfl_sync(0xffffffffu, hA2, 1, 4);
                a2 = __shfl_sync(0xffffffffu, hA2, 2, 4);
                a3 = __shfl_sync(0xffffffffu, hA2, 3, 4);
                e0 = __shfl_sync(0xffffffffu, hB2, 0, 4);
                e1 = __shfl_sync(0xffffffffu, hB2, 1, 4);
                e2 = __shfl_sync(0xffffffffu, hB2, 2, 4);
                e3 = __shfl_sync(0xffffffffu, hB2, 3, 4);

                cA0 = nA0; cA1 = nA1; cB0 = nB0; cB1 = nB1;
            }
            __syncthreads();
        }

        g_hf[(blk_b0 + bA) * 4 + j] = 0.5f * hA2;
        g_hf[(blk_b0 + bB) * 4 + j] = 0.5f * hB2;
    }
}

// =====================================================================
// Kernel 3: tail. 128 blocks x 384 threads; warp w reduces one live gate
// row (i: 0-3, g: 8-11, o: 12-15). f-gate provably unused (c0 = 0).
// =====================================================================
__global__ __launch_bounds__(384) void tail_kernel(const float* __restrict__ x,
                                                   const float* __restrict__ Wihb,
                                                   const float* __restrict__ bihb,
                                                   const float* __restrict__ bhhb,
                                                   const float* __restrict__ Wout,
                                                   const float* __restrict__ bout,
                                                   float* __restrict__ out) {
    const int b = blockIdx.x;
    const int tid = threadIdx.x;
    const int w = tid >> 5;
    const int l = tid & 31;
    const int gr = (w < 4) ? w : (w + 4);    // gate row: 0-3, 8-11, 12-15

    __shared__ float sg[12];

    const float* xr = x + ((size_t)b * TSEQ + (TSEQ - 1)) * KIN;
    const float* wr = Wihb + (size_t)gr * KIN;

    float a = 0.f;
    for (int k = l; k < KIN; k += 32)
        a = fmaf(__ldg(&xr[k]), __ldg(&wr[k]), a);
#pragma unroll
    for (int s = 16; s > 0; s >>= 1)
        a += __shfl_xor_sync(0xffffffffu, a, s);
    if (l == 0) sg[w] = a + __ldg(&bihb[gr]) + __ldg(&bhhb[gr]);
    __syncthreads();

    if (tid == 0) {
        float hb[4], hf[4];
#pragma unroll
        for (int jj = 0; jj < 4; ++jj) {
            float iv = sigmoid_acc(sg[jj]);
            float gv = tanh_acc(sg[4 + jj]);
            float ov = sigmoid_acc(sg[8 + jj]);
            float cc = iv * gv;                 // c0 = 0 => f-gate drops out
            hb[jj] = ov * tanh_acc(cc);
            hf[jj] = g_hf[b * 4 + jj];
        }
#pragma unroll
        for (int o2 = 0; o2 < 2; ++o2) {
            float s = __ldg(&bout[o2]);
#pragma unroll
            for (int jj = 0; jj < 4; ++jj) {
                s = fmaf(__ldg(&Wout[o2 * 8 + jj]),     hf[jj], s);
                s = fmaf(__ldg(&Wout[o2 * 8 + 4 + jj]), hb[jj], s);
            }
            out[b * 2 + o2] = s;
        }
    }
}

// =====================================================================
extern "C" void kernel_launch(void* const* d_in, const int* in_sizes, int n_in,
                              void* d_out, int out_size) {
    const float* x    = (const float*)d_in[0];
    const float* Wihf = (const float*)d_in[1];
    const float* Whhf = (const float*)d_in[2];
    const float* bihf = (const float*)d_in[3];
    const float* bhhf = (const float*)d_in[4];
    const float* Wihb = (const float*)d_in[5];
    // d_in[6] = W_hh_b: provably unused (backward output only needs step 1 from zero state)
    const float* bihb = (const float*)d_in[7];
    const float* bhhb = (const float*)d_in[8];
    const float* Wout = (const float*)d_in[9];
    const float* bout = (const float*)d_in[10];
    float* out = (float*)d_out;

    constexpr int LSTM_SMEM = 2 * 2 * 16 * 16 * 16 * 4;   // 65536 B
    static bool attr_set = false;
    if (!attr_set) {
        cudaFuncSetAttribute(lstm_fwd_kernel, cudaFuncAttributeMaxDynamicSharedMemorySize, LSTM_SMEM);
        attr_set = true;
    }

    dim3 pgrid(BATCH * TSEQ / PROWS, 2);   // (128, 2)
    proj_kernel<<<pgrid, 128>>>(x, Wihf, bihf, bhhf);
    lstm_fwd_kernel<<<8, 64, LSTM_SMEM>>>(Whhf);
    tail_kernel<<<BATCH, 384>>>(x, Wihb, bihb, bhhb, Wout, bout, out);
}

// round 14
// speedup vs baseline: 1.1630x; 1.0773x over previous
#include <cuda_runtime.h>

// Problem constants
constexpr int BATCH = 128;
constexpr int TSEQ  = 512;
constexpr int KIN   = 906;
constexpr int NG    = 16;       // 4*H gates
constexpr int KHALF = 453;      // K split
constexpr int CK    = 16;       // k per chunk
constexpr int NCHK  = 29;       // 28*16 + 5
constexpr int PROWS = 256;      // rows per proj block
constexpr int PITCH = 258;      // k-major tile pitch (floats)

// Scratch (device globals; no allocation allowed)
// K-half partials, layout [t][b][j][ifgo]; i/f/o pre-scaled 0.5 (sigmoid fold)
__device__ __align__(16) float g_xph[2][BATCH * TSEQ * NG];
__device__ float g_hf[BATCH * 4];

// ---------- packed fp32x2 helpers (Blackwell FFMA2) ----------
__device__ __forceinline__ unsigned long long pack2(float x) {
    unsigned long long r;
    asm("mov.b64 %0, {%1, %1};" : "=l"(r) : "f"(x));
    return r;
}
__device__ __forceinline__ unsigned long long fma2(unsigned long long a,
                                                   unsigned long long b,
                                                   unsigned long long c) {
    unsigned long long d;
    asm("fma.rn.f32x2 %0, %1, %2, %3;" : "=l"(d) : "l"(a), "l"(b), "l"(c));
    return d;
}
__device__ __forceinline__ void unpack2(unsigned long long a, float& lo, float& hi) {
    asm("mov.b64 {%0, %1}, %2;" : "=f"(lo), "=f"(hi) : "l"(a));
}

// ---------- activations ----------
__device__ __forceinline__ float tanha(float x) {
    float r;
    asm("tanh.approx.f32 %0, %1;" : "=f"(r) : "f"(x));
    return r;
}
__device__ __forceinline__ float sigmoid_acc(float x) {
    float e = __expf(-x);
    return __fdividef(1.0f, 1.0f + e);
}
__device__ __forceinline__ float tanh_acc(float x) {
    float e = __expf(2.0f * x);
    return 1.0f - __fdividef(2.0f, 1.0f + e);
}

// ---------- cp.async 16B (lstm feed) ----------
__device__ __forceinline__ void cp16(void* dst, const void* src) {
    unsigned d = (unsigned)__cvta_generic_to_shared(dst);
    asm volatile("cp.async.cg.shared.global [%0], [%1], 16;" :: "r"(d), "l"(src));
}

// =====================================================================
// Kernel 1: projection (R10 version — best measured: 86 us).
// grid (256, 2); 128 threads; R=2 rows/thread; static depth-2 register
// staging (xr0/xr1), loop unrolled by 2 so bank choice is compile-time.
// =====================================================================
__global__ __launch_bounds__(128) void proj_kernel(const float* __restrict__ x,
                                                   const float* __restrict__ Wih,
                                                   const float* __restrict__ bih,
                                                   const float* __restrict__ bhh) {
    __shared__ __align__(16) float sxT[2][CK * PITCH];  // [buf][k][row]
    __shared__ __align__(16) float sw[2][CK * 16];      // [buf][k][gate]

    const int tid  = threadIdx.x;
    const int lane = tid & 31;
    const int wid  = tid >> 5;
    const int half = blockIdx.y;
    const int kb   = half * KHALF;
    const size_t row0 = (size_t)blockIdx.x * PROWS;

    const int kk_l = lane & 15;     // k within chunk
    const int rs   = lane >> 4;     // row sub (0/1)

    unsigned long long accA[8], accB[8];
#pragma unroll
    for (int m = 0; m < 8; ++m) { accA[m] = 0ull; accB[m] = 0ull; }

    float xr0[32], xr1[32];   // STATIC depth-2 banks
    float wr0[2],  wr1[2];

    auto ldg_chunk = [&](int ch, float (&xr)[32], float (&wr)[2]) {
        const int kloc = ch * CK + kk_l;
        const bool ok = kloc < KHALF;
        const float* xp = x + (row0 + 64 * wid + rs) * KIN + kb + kloc;
#pragma unroll
        for (int i = 0; i < 32; ++i)
            xr[i] = ok ? __ldg(xp + (size_t)2 * i * KIN) : 0.0f;
#pragma unroll
        for (int u = 0; u < 2; ++u) {
            const int idx = tid + 128 * u;
            const int kw = idx >> 4, g = idx & 15;
            const int kwl = ch * CK + kw;
            const float sc = (g >= 8 && g < 12) ? 1.0f : 0.5f;
            wr[u] = (kwl < KHALF) ? sc * __ldg(Wih + (size_t)g * KIN + kb + kwl) : 0.0f;
        }
    };
    auto sts_chunk = [&](const float (&xr)[32], const float (&wr)[2], int buf) {
        float* sx = sxT[buf];
#pragma unroll
        for (int i = 0; i < 32; ++i)
            sx[kk_l * PITCH + 64 * wid + rs + 2 * i] = xr[i];
        float* swp = sw[buf];
#pragma unroll
        for (int u = 0; u < 2; ++u)
            swp[tid + 128 * u] = wr[u];    // [k][g] layout: idx = k*16+g
    };

#define PROJ_K(SX, SW, KK)                                                     \
    {                                                                          \
        const float2 xv = *(const float2*)((SX) + (KK) * PITCH + 2 * tid);     \
        const unsigned long long xa = pack2(xv.x);                             \
        const unsigned long long xb = pack2(xv.y);                             \
        const ulonglong2* wr = (const ulonglong2*)((SW) + (KK) * 16);          \
        ulonglong2 w0 = wr[0], w1 = wr[1];                                     \
        accA[0] = fma2(xa, w0.x, accA[0]);  accB[0] = fma2(xb, w0.x, accB[0]); \
        accA[1] = fma2(xa, w0.y, accA[1]);  accB[1] = fma2(xb, w0.y, accB[1]); \
        accA[2] = fma2(xa, w1.x, accA[2]);  accB[2] = fma2(xb, w1.x, accB[2]); \
        accA[3] = fma2(xa, w1.y, accA[3]);  accB[3] = fma2(xb, w1.y, accB[3]); \
        ulonglong2 w2 = wr[2], w3 = wr[3];                                     \
        accA[4] = fma2(xa, w2.x, accA[4]);  accB[4] = fma2(xb, w2.x, accB[4]); \
        accA[5] = fma2(xa, w2.y, accA[5]);  accB[5] = fma2(xb, w2.y, accB[5]); \
        accA[6] = fma2(xa, w3.x, accA[6]);  accB[6] = fma2(xb, w3.x, accB[6]); \
        accA[7] = fma2(xa, w3.y, accA[7]);  accB[7] = fma2(xb, w3.y, accB[7]); \
    }

    ldg_chunk(0, xr0, wr0);
    ldg_chunk(1, xr1, wr1);
    sts_chunk(xr0, wr0, 0);
    __syncthreads();

#pragma unroll 1
    for (int c2 = 0; c2 < 14; ++c2) {
        const int ch = 2 * c2;
        ldg_chunk(ch + 2, xr0, wr0);
        {
            const float* sx = sxT[0];
            const float* swp = sw[0];
#pragma unroll
            for (int kk = 0; kk < CK; ++kk) PROJ_K(sx, swp, kk)
        }
        sts_chunk(xr1, wr1, 1);
        __syncthreads();
        if (ch + 3 < NCHK) ldg_chunk(ch + 3, xr1, wr1);
        {
            const float* sx = sxT[1];
            const float* swp = sw[1];
#pragma unroll
            for (int kk = 0; kk < CK; ++kk) PROJ_K(sx, swp, kk)
        }
        sts_chunk(xr0, wr0, 0);
        __syncthreads();
    }
    {
        const float* sx = sxT[0];
        const float* swp = sw[0];
#pragma unroll
        for (int kk = 0; kk < KHALF - CK * (NCHK - 1); ++kk) PROJ_K(sx, swp, kk)
    }
#undef PROJ_K

    float va[16], vb[16];
#pragma unroll
    for (int m = 0; m < 8; ++m) { unpack2(accA[m], va[2*m], va[2*m+1]);
                                  unpack2(accB[m], vb[2*m], vb[2*m+1]); }
    if (half == 0) {
#pragma unroll
        for (int g = 0; g < 16; ++g) {
            const float sc = (g >= 8 && g < 12) ? 1.0f : 0.5f;
            const float b = sc * (__ldg(&bih[g]) + __ldg(&bhh[g]));
            va[g] += b; vb[g] += b;
        }
    }

    float4* dst = reinterpret_cast<float4*>(g_xph[half]);
    const size_t rA = row0 + 2 * tid;
    const size_t tA = rA & 511, bA = rA >> 9;
    const size_t tB = (rA + 1) & 511, bB = (rA + 1) >> 9;
#pragma unroll
    for (int j = 0; j < 4; ++j) {
        dst[(tA * 128 + bA) * 4 + j] = make_float4(va[j], va[4+j], va[8+j], va[12+j]);
        dst[(tB * 128 + bB) * 4 + j] = make_float4(vb[j], vb[4+j], vb[8+j], vb[12+j]);
    }
}

// =====================================================================
// Kernel 2: forward LSTM — 16 blocks x 64 threads, SINGLE stream/warp:
// warp0 = compute (8 batches, 4 lanes/batch), warp1 = copy (cp.async,
// 16-step stages, both halves, double-buffered; 32 KB smem).
// Single stream: per-warp MUFU floor 40 cyc (vs dual 80); chain ~105.
// =====================================================================
__global__ __launch_bounds__(64) void lstm_fwd_kernel(const float* __restrict__ Whh) {
    __shared__ __align__(16) float sx[2 * 2 * 16 * 8 * 16];  // [p][h][tt][bb(8)][16] = 32 KB
    auto buf_at = [&](int p, int h, int tt, int b) -> float* {
        return sx + ((((p * 2 + h) * 16 + tt) * 8) + b) * 16;
    };

    const int tid = threadIdx.x;
    const int blk_b0 = blockIdx.x * 8;

    if (tid >= 32) {
        // ---------------- copy warp ----------------
        const int l  = tid & 31;
        const int bb = l & 7;          // batch 0..7
        const int f0 = (l >> 3) * 4;   // float4 slot
        auto fill = [&](int s) {
            const int t0 = s * 16;
            const int p = s & 1;
#pragma unroll
            for (int h = 0; h < 2; ++h) {
                const float* base = g_xph[h];
#pragma unroll
                for (int tt = 0; tt < 16; ++tt) {
                    const float* src = base + (((size_t)(t0 + tt) * 128) + blk_b0 + bb) * 16 + f0;
                    cp16(buf_at(p, h, tt, bb) + f0, src);
                }
            }
        };
        fill(0);
        asm volatile("cp.async.commit_group;");
        asm volatile("cp.async.wait_group 0;" ::: "memory");
        __syncthreads();
        for (int s = 0; s < 32; ++s) {
            if (s + 1 < 32) {
                fill(s + 1);
                asm volatile("cp.async.commit_group;");
                asm volatile("cp.async.wait_group 0;" ::: "memory");
            }
            __syncthreads();
        }
    } else {
        // ---------------- compute warp ----------------
        const int j  = tid & 3;
        const int pr = tid >> 2;       // 0..7
        const int bA = pr;

        // 0.25 = 0.5(sigmoid fold) * 0.5(h2 fold); g-gate 0.5 (h2 fold only)
        float wi[4], wf[4], wg[4], wo[4];
#pragma unroll
        for (int k = 0; k < 4; ++k) {
            wi[k] = 0.25f * __ldg(&Whh[(0  + j) * 4 + k]);
            wf[k] = 0.25f * __ldg(&Whh[(4  + j) * 4 + k]);
            wg[k] = 0.50f * __ldg(&Whh[(8  + j) * 4 + k]);
            wo[k] = 0.25f * __ldg(&Whh[(12 + j) * 4 + k]);
        }

        float a0 = 0.f, a1 = 0.f, a2 = 0.f, a3 = 0.f, cA = 0.f, hA2 = 0.f;

        __syncthreads();   // matches copy prologue sync

        for (int s = 0; s < 32; ++s) {
            const int p = s & 1;
            float4 cA0 = *reinterpret_cast<const float4*>(buf_at(p, 0, 0, bA) + 4 * j);
            float4 cA1 = *reinterpret_cast<const float4*>(buf_at(p, 1, 0, bA) + 4 * j);
#pragma unroll
            for (int tt = 0; tt < 16; ++tt) {
                float4 nA0, nA1;
                if (tt < 15) {
                    nA0 = *reinterpret_cast<const float4*>(buf_at(p, 0, tt + 1, bA) + 4 * j);
                    nA1 = *reinterpret_cast<const float4*>(buf_at(p, 1, tt + 1, bA) + 4 * j);
                }

                // balanced trees; half-1 partial folded into second tree
                float ip = fmaf(wi[1], a1, fmaf(wi[0], a0, cA0.x)) + fmaf(wi[3], a3, fmaf(wi[2], a2, cA1.x));
                float fp = fmaf(wf[1], a1, fmaf(wf[0], a0, cA0.y)) + fmaf(wf[3], a3, fmaf(wf[2], a2, cA1.y));
                float gp = fmaf(wg[1], a1, fmaf(wg[0], a0, cA0.z)) + fmaf(wg[3], a3, fmaf(wg[2], a2, cA1.z));
                float op = fmaf(wo[1], a1, fmaf(wo[0], a0, cA0.w)) + fmaf(wo[3], a3, fmaf(wo[2], a2, cA1.w));

                const float ti = tanha(ip), tf = tanha(fp), tg = tanha(gp), to = tanha(op);

                cA = 0.5f * (fmaf(tf, cA, cA) + fmaf(ti, tg, tg));

                const float tc = tanha(cA);
                hA2 = fmaf(to, tc, tc);   // = 2*h

                a0 = __shfl_sync(0xffffffffu, hA2, 0, 4);
                a1 = __shfl_sync(0xffffffffu, hA2, 1, 4);
                a2 = __shfl_sync(0xffffffffu, hA2, 2, 4);
                a3 = __shfl_sync(0xffffffffu, hA2, 3, 4);

                cA0 = nA0; cA1 = nA1;
            }
            __syncthreads();
        }

        g_hf[(blk_b0 + bA) * 4 + j] = 0.5f * hA2;
    }
}

// =====================================================================
// Kernel 3: tail. 128 blocks x 384 threads; warp w reduces one live gate
// row (i: 0-3, g: 8-11, o: 12-15). f-gate provably unused (c0 = 0).
// =====================================================================
__global__ __launch_bounds__(384) void tail_kernel(const float* __restrict__ x,
                                                   const float* __restrict__ Wihb,
                                                   const float* __restrict__ bihb,
                                                   const float* __restrict__ bhhb,
                                                   const float* __restrict__ Wout,
                                                   const float* __restrict__ bout,
                                                   float* __restrict__ out) {
    const int b = blockIdx.x;
    const int tid = threadIdx.x;
    const int w = tid >> 5;
    const int l = tid & 31;
    const int gr = (w < 4) ? w : (w + 4);    // gate row: 0-3, 8-11, 12-15

    __shared__ float sg[12];

    const float* xr = x + ((size_t)b * TSEQ + (TSEQ - 1)) * KIN;
    const float* wr = Wihb + (size_t)gr * KIN;

    float a = 0.f;
    for (int k = l; k < KIN; k += 32)
        a = fmaf(__ldg(&xr[k]), __ldg(&wr[k]), a);
#pragma unroll
    for (int s = 16; s > 0; s >>= 1)
        a += __shfl_xor_sync(0xffffffffu, a, s);
    if (l == 0) sg[w] = a + __ldg(&bihb[gr]) + __ldg(&bhhb[gr]);
    __syncthreads();

    if (tid == 0) {
        float hb[4], hf[4];
#pragma unroll
        for (int jj = 0; jj < 4; ++jj) {
            float iv = sigmoid_acc(sg[jj]);
            float gv = tanh_acc(sg[4 + jj]);
            float ov = sigmoid_acc(sg[8 + jj]);
            float cc = iv * gv;                 // c0 = 0 => f-gate drops out
            hb[jj] = ov * tanh_acc(cc);
            hf[jj] = g_hf[b * 4 + jj];
        }
#pragma unroll
        for (int o2 = 0; o2 < 2; ++o2) {
            float s = __ldg(&bout[o2]);
#pragma unroll
            for (int jj = 0; jj < 4; ++jj) {
                s = fmaf(__ldg(&Wout[o2 * 8 + jj]),     hf[jj], s);
                s = fmaf(__ldg(&Wout[o2 * 8 + 4 + jj]), hb[jj], s);
            }
            out[b * 2 + o2] = s;
        }
    }
}

// =====================================================================
extern "C" void kernel_launch(void* const* d_in, const int* in_sizes, int n_in,
                              void* d_out, int out_size) {
    const float* x    = (const float*)d_in[0];
    const float* Wihf = (const float*)d_in[1];
    const float* Whhf = (const float*)d_in[2];
    const float* bihf = (const float*)d_in[3];
    const float* bhhf = (const float*)d_in[4];
    const float* Wihb = (const float*)d_in[5];
    // d_in[6] = W_hh_b: provably unused (backward output only needs step 1 from zero state)
    const float* bihb = (const float*)d_in[7];
    const float* bhhb = (const float*)d_in[8];
    const float* Wout = (const float*)d_in[9];
    const float* bout = (const float*)d_in[10];
    float* out = (float*)d_out;

    dim3 pgrid(BATCH * TSEQ / PROWS, 2);   // (256, 2)
    proj_kernel<<<pgrid, 128>>>(x, Wihf, bihf, bhhf);
    lstm_fwd_kernel<<<16, 64>>>(Whhf);
    tail_kernel<<<BATCH, 384>>>(x, Wihb, bihb, bhhb, Wout, bout, out);
}

// round 15
// speedup vs baseline: 1.3589x; 1.1684x over previous
#include <cuda_runtime.h>

// Problem constants
constexpr int BATCH = 128;
constexpr int TSEQ  = 512;
constexpr int KIN   = 906;
constexpr int NG    = 16;       // 4*H gates
constexpr int KHALF = 453;      // K split
constexpr int CK    = 16;       // k per chunk
constexpr int NCHK  = 29;       // 28*16 + 5
constexpr int PROWS = 256;      // rows per proj unit
constexpr int PITCH = 258;      // k-major tile pitch (floats)
constexpr int SMEM_BYTES = (2 * CK * PITCH + 2 * CK * 16) * 4;  // 35072 (>= lstm's 32768)

// Scratch (device globals; no allocation allowed)
// K-half partials, layout [t][b][j][ifgo]; i/f/o pre-scaled 0.5 (sigmoid fold)
__device__ __align__(16) float g_xph[2][BATCH * TSEQ * NG];
__device__ float g_hf[BATCH * 4];
__device__ unsigned g_flag[32];   // [group(16)][part(2)] counters, target 16; reset by tail

// ---------- packed fp32x2 helpers (Blackwell FFMA2) ----------
__device__ __forceinline__ unsigned long long pack2(float x) {
    unsigned long long r;
    asm("mov.b64 %0, {%1, %1};" : "=l"(r) : "f"(x));
    return r;
}
__device__ __forceinline__ unsigned long long fma2(unsigned long long a,
                                                   unsigned long long b,
                                                   unsigned long long c) {
    unsigned long long d;
    asm("fma.rn.f32x2 %0, %1, %2, %3;" : "=l"(d) : "l"(a), "l"(b), "l"(c));
    return d;
}
__device__ __forceinline__ void unpack2(unsigned long long a, float& lo, float& hi) {
    asm("mov.b64 {%0, %1}, %2;" : "=f"(lo), "=f"(hi) : "l"(a));
}

// ---------- activations ----------
__device__ __forceinline__ float tanha(float x) {
    float r;
    asm("tanh.approx.f32 %0, %1;" : "=f"(r) : "f"(x));
    return r;
}
__device__ __forceinline__ float sigmoid_acc(float x) {
    float e = __expf(-x);
    return __fdividef(1.0f, 1.0f + e);
}
__device__ __forceinline__ float tanh_acc(float x) {
    float e = __expf(2.0f * x);
    return 1.0f - __fdividef(2.0f, 1.0f + e);
}

// ---------- cp.async 16B (lstm feed; .cg -> L2, coherent with fence+flag) ----------
__device__ __forceinline__ void cp16(void* dst, const void* src) {
    unsigned d = (unsigned)__cvta_generic_to_shared(dst);
    asm volatile("cp.async.cg.shared.global [%0], [%1], 16;" :: "r"(d), "l"(src));
}

// =====================================================================
// proj body (R14 verbatim; params instead of blockIdx; + completion signal)
// =====================================================================
__device__ void proj_body(float* smem, const float* __restrict__ x,
                          const float* __restrict__ Wih,
                          const float* __restrict__ bih,
                          const float* __restrict__ bhh,
                          int batch, int part, int half) {
    float* const sxT[2] = { smem, smem + CK * PITCH };
    float* const swb[2] = { smem + 2 * CK * PITCH, smem + 2 * CK * PITCH + CK * 16 };

    const int tid  = threadIdx.x;
    const int lane = tid & 31;
    const int wid  = tid >> 5;
    const int kb   = half * KHALF;
    const size_t row0 = (size_t)(batch * 2 + part) * PROWS;

    const int kk_l = lane & 15;     // k within chunk
    const int rs   = lane >> 4;     // row sub (0/1)

    unsigned long long accA[8], accB[8];
#pragma unroll
    for (int m = 0; m < 8; ++m) { accA[m] = 0ull; accB[m] = 0ull; }

    float xr0[32], xr1[32];   // STATIC depth-2 banks
    float wr0[2],  wr1[2];

    auto ldg_chunk = [&](int ch, float (&xr)[32], float (&wr)[2]) {
        const int kloc = ch * CK + kk_l;
        const bool ok = kloc < KHALF;
        const float* xp = x + (row0 + 64 * wid + rs) * KIN + kb + kloc;
#pragma unroll
        for (int i = 0; i < 32; ++i)
            xr[i] = ok ? __ldg(xp + (size_t)2 * i * KIN) : 0.0f;
#pragma unroll
        for (int u = 0; u < 2; ++u) {
            const int idx = tid + 128 * u;
            const int kw = idx >> 4, g = idx & 15;
            const int kwl = ch * CK + kw;
            const float sc = (g >= 8 && g < 12) ? 1.0f : 0.5f;
            wr[u] = (kwl < KHALF) ? sc * __ldg(Wih + (size_t)g * KIN + kb + kwl) : 0.0f;
        }
    };
    auto sts_chunk = [&](const float (&xr)[32], const float (&wr)[2], int buf) {
        float* sx = sxT[buf];
#pragma unroll
        for (int i = 0; i < 32; ++i)
            sx[kk_l * PITCH + 64 * wid + rs + 2 * i] = xr[i];
        float* swp = swb[buf];
#pragma unroll
        for (int u = 0; u < 2; ++u)
            swp[tid + 128 * u] = wr[u];    // [k][g] layout: idx = k*16+g
    };

#define PROJ_K(SX, SW, KK)                                                     \
    {                                                                          \
        const float2 xv = *(const float2*)((SX) + (KK) * PITCH + 2 * tid);     \
        const unsigned long long xa = pack2(xv.x);                             \
        const unsigned long long xb = pack2(xv.y);                             \
        const ulonglong2* wr = (const ulonglong2*)((SW) + (KK) * 16);          \
        ulonglong2 w0 = wr[0], w1 = wr[1];                                     \
        accA[0] = fma2(xa, w0.x, accA[0]);  accB[0] = fma2(xb, w0.x, accB[0]); \
        accA[1] = fma2(xa, w0.y, accA[1]);  accB[1] = fma2(xb, w0.y, accB[1]); \
        accA[2] = fma2(xa, w1.x, accA[2]);  accB[2] = fma2(xb, w1.x, accB[2]); \
        accA[3] = fma2(xa, w1.y, accA[3]);  accB[3] = fma2(xb, w1.y, accB[3]); \
        ulonglong2 w2 = wr[2], w3 = wr[3];                                     \
        accA[4] = fma2(xa, w2.x, accA[4]);  accB[4] = fma2(xb, w2.x, accB[4]); \
        accA[5] = fma2(xa, w2.y, accA[5]);  accB[5] = fma2(xb, w2.y, accB[5]); \
        accA[6] = fma2(xa, w3.x, accA[6]);  accB[6] = fma2(xb, w3.x, accB[6]); \
        accA[7] = fma2(xa, w3.y, accA[7]);  accB[7] = fma2(xb, w3.y, accB[7]); \
    }

    ldg_chunk(0, xr0, wr0);
    ldg_chunk(1, xr1, wr1);
    sts_chunk(xr0, wr0, 0);
    __syncthreads();

#pragma unroll 1
    for (int c2 = 0; c2 < 14; ++c2) {
        const int ch = 2 * c2;
        ldg_chunk(ch + 2, xr0, wr0);
        {
            const float* sx = sxT[0];
            const float* swp = swb[0];
#pragma unroll
            for (int kk = 0; kk < CK; ++kk) PROJ_K(sx, swp, kk)
        }
        sts_chunk(xr1, wr1, 1);
        __syncthreads();
        if (ch + 3 < NCHK) ldg_chunk(ch + 3, xr1, wr1);
        {
            const float* sx = sxT[1];
            const float* swp = swb[1];
#pragma unroll
            for (int kk = 0; kk < CK; ++kk) PROJ_K(sx, swp, kk)
        }
        sts_chunk(xr0, wr0, 0);
        __syncthreads();
    }
    {
        const float* sx = sxT[0];
        const float* swp = swb[0];
#pragma unroll
        for (int kk = 0; kk < KHALF - CK * (NCHK - 1); ++kk) PROJ_K(sx, swp, kk)
    }
#undef PROJ_K

    float va[16], vb[16];
#pragma unroll
    for (int m = 0; m < 8; ++m) { unpack2(accA[m], va[2*m], va[2*m+1]);
                                  unpack2(accB[m], vb[2*m], vb[2*m+1]); }
    if (half == 0) {
#pragma unroll
        for (int g = 0; g < 16; ++g) {
            const float sc = (g >= 8 && g < 12) ? 1.0f : 0.5f;
            const float b = sc * (__ldg(&bih[g]) + __ldg(&bhh[g]));
            va[g] += b; vb[g] += b;
        }
    }

    float4* dst = reinterpret_cast<float4*>(g_xph[half]);
    const size_t rA = row0 + 2 * tid;
    const size_t tA = rA & 511, bA = rA >> 9;
    const size_t tB = (rA + 1) & 511, bB = (rA + 1) >> 9;
#pragma unroll
    for (int j = 0; j < 4; ++j) {
        dst[(tA * 128 + bA) * 4 + j] = make_float4(va[j], va[4+j], va[8+j], va[12+j]);
        dst[(tB * 128 + bB) * 4 + j] = make_float4(vb[j], vb[4+j], vb[8+j], vb[12+j]);
    }

    // completion signal for the lstm consumer
    __syncthreads();
    if (tid == 0) {
        __threadfence();
        atomicAdd(&g_flag[(batch >> 3) * 2 + part], 1u);
    }
}

// =====================================================================
// lstm body (R14 verbatim + flag-gated copy warp). blk in [0,16):
// 8 batches/block; warp0 compute, warp1 copy, warps 2-3 sync-idle.
// =====================================================================
__device__ void lstm_body(float* smem, const float* __restrict__ Whh, int blk) {
    auto buf_at = [&](int p, int h, int tt, int b) -> float* {
        return smem + ((((p * 2 + h) * 16 + tt) * 8) + b) * 16;
    };

    const int tid = threadIdx.x;
    const int wid = tid >> 5;
    const int blk_b0 = blk * 8;
    const int group = blk >> 1;     // batch group of 8 = blk_b0>>3

    if (wid == 1) {
        // ---------------- copy warp ----------------
        const int l  = tid & 31;
        const int bb = l & 7;          // batch 0..7
        const int f0 = (l >> 3) * 4;   // float4 slot
        auto wait_part = [&](int part) {
            volatile unsigned* f = &g_flag[group * 2 + part];
            while (*f < 16u) __nanosleep(64);
            __threadfence();
        };
        auto fill = [&](int s) {
            const int t0 = s * 16;
            const int p = s & 1;
#pragma unroll
            for (int h = 0; h < 2; ++h) {
                const float* base = g_xph[h];
#pragma unroll
                for (int tt = 0; tt < 16; ++tt) {
                    const float* src = base + (((size_t)(t0 + tt) * 128) + blk_b0 + bb) * 16 + f0;
                    cp16(buf_at(p, h, tt, bb) + f0, src);
                }
            }
        };
        wait_part(0);
        fill(0);
        asm volatile("cp.async.commit_group;");
        asm volatile("cp.async.wait_group 0;" ::: "memory");
        __syncthreads();
        for (int s = 0; s < 32; ++s) {
            if (s + 1 < 32) {
                if (s + 1 == 16) wait_part(1);
                fill(s + 1);
                asm volatile("cp.async.commit_group;");
                asm volatile("cp.async.wait_group 0;" ::: "memory");
            }
            __syncthreads();
        }
    } else if (wid == 0) {
        // ---------------- compute warp ----------------
        const int j  = tid & 3;
        const int pr = tid >> 2;       // 0..7
        const int bA = pr;

        // 0.25 = 0.5(sigmoid fold) * 0.5(h2 fold); g-gate 0.5 (h2 fold only)
        float wi[4], wf[4], wg[4], wo[4];
#pragma unroll
        for (int k = 0; k < 4; ++k) {
            wi[k] = 0.25f * __ldg(&Whh[(0  + j) * 4 + k]);
            wf[k] = 0.25f * __ldg(&Whh[(4  + j) * 4 + k]);
            wg[k] = 0.50f * __ldg(&Whh[(8  + j) * 4 + k]);
            wo[k] = 0.25f * __ldg(&Whh[(12 + j) * 4 + k]);
        }

        float a0 = 0.f, a1 = 0.f, a2 = 0.f, a3 = 0.f, cA = 0.f, hA2 = 0.f;

        __syncthreads();   // matches copy prologue sync

        for (int s = 0; s < 32; ++s) {
            const int p = s & 1;
            float4 cA0 = *reinterpret_cast<const float4*>(buf_at(p, 0, 0, bA) + 4 * j);
            float4 cA1 = *reinterpret_cast<const float4*>(buf_at(p, 1, 0, bA) + 4 * j);
#pragma unroll
            for (int tt = 0; tt < 16; ++tt) {
                float4 nA0, nA1;
                if (tt < 15) {
                    nA0 = *reinterpret_cast<const float4*>(buf_at(p, 0, tt + 1, bA) + 4 * j);
                    nA1 = *reinterpret_cast<const float4*>(buf_at(p, 1, tt + 1, bA) + 4 * j);
                }

                float ip = fmaf(wi[1], a1, fmaf(wi[0], a0, cA0.x)) + fmaf(wi[3], a3, fmaf(wi[2], a2, cA1.x));
                float fp = fmaf(wf[1], a1, fmaf(wf[0], a0, cA0.y)) + fmaf(wf[3], a3, fmaf(wf[2], a2, cA1.y));
                float gp = fmaf(wg[1], a1, fmaf(wg[0], a0, cA0.z)) + fmaf(wg[3], a3, fmaf(wg[2], a2, cA1.z));
                float op = fmaf(wo[1], a1, fmaf(wo[0], a0, cA0.w)) + fmaf(wo[3], a3, fmaf(wo[2], a2, cA1.w));

                const float ti = tanha(ip), tf = tanha(fp), tg = tanha(gp), to = tanha(op);

                cA = 0.5f * (fmaf(tf, cA, cA) + fmaf(ti, tg, tg));

                const float tc = tanha(cA);
                hA2 = fmaf(to, tc, tc);   // = 2*h

                a0 = __shfl_sync(0xffffffffu, hA2, 0, 4);
                a1 = __shfl_sync(0xffffffffu, hA2, 1, 4);
                a2 = __shfl_sync(0xffffffffu, hA2, 2, 4);
                a3 = __shfl_sync(0xffffffffu, hA2, 3, 4);

                cA0 = nA0; cA1 = nA1;
            }
            __syncthreads();
        }

        g_hf[(blk_b0 + bA) * 4 + j] = 0.5f * hA2;
    } else {
        // idle warps: participate in all 33 block syncs
        for (int i = 0; i < 33; ++i) __syncthreads();
    }
}

// =====================================================================
// Kernel 1: fused proj + lstm. Grid 528 x 128 threads.
// bids 0-15: lstm (16 blocks). bids 16-527: proj, mapped so ALL part-0
// (t<256) units occupy low bids -> they complete in wave 1 and lstm
// overlaps wave 2.
// =====================================================================
__global__ __launch_bounds__(128) void fused_kernel(const float* __restrict__ x,
                                                    const float* __restrict__ Wih,
                                                    const float* __restrict__ bih,
                                                    const float* __restrict__ bhh,
                                                    const float* __restrict__ Whh) {
    extern __shared__ float smem[];
    const int bid = blockIdx.x;
    if (bid >= 16) {
        const int u = bid - 16;             // 0..511
        const int part = u >> 8;            // part 0 first (low bids)
        const int v = u & 255;
        const int batch = v >> 1;
        const int half = v & 1;
        proj_body(smem, x, Wih, bih, bhh, batch, part, half);
    } else {
        lstm_body(smem, Whh, bid);
    }
}

// =====================================================================
// Kernel 2: tail. 128 blocks x 384 threads; warp w reduces one live gate
// row (i: 0-3, g: 8-11, o: 12-15). f-gate provably unused (c0 = 0).
// Block 0 also resets g_flag for the next (graph-replayed) launch.
// =====================================================================
__global__ __launch_bounds__(384) void tail_kernel(const float* __restrict__ x,
                                                   const float* __restrict__ Wihb,
                                                   const float* __restrict__ bihb,
                                                   const float* __restrict__ bhhb,
                                                   const float* __restrict__ Wout,
                                                   const float* __restrict__ bout,
                                                   float* __restrict__ out) {
    const int b = blockIdx.x;
    const int tid = threadIdx.x;
    const int w = tid >> 5;
    const int l = tid & 31;
    const int gr = (w < 4) ? w : (w + 4);    // gate row: 0-3, 8-11, 12-15

    __shared__ float sg[12];

    if (b == 0 && tid >= 352) g_flag[tid - 352] = 0u;   // reset 32 flags

    const float* xr = x + ((size_t)b * TSEQ + (TSEQ - 1)) * KIN;
    const float* wr = Wihb + (size_t)gr * KIN;

    float a = 0.f;
    for (int k = l; k < KIN; k += 32)
        a = fmaf(__ldg(&xr[k]), __ldg(&wr[k]), a);
#pragma unroll
    for (int s = 16; s > 0; s >>= 1)
        a += __shfl_xor_sync(0xffffffffu, a, s);
    if (l == 0) sg[w] = a + __ldg(&bihb[gr]) + __ldg(&bhhb[gr]);
    __syncthreads();

    if (tid == 0) {
        float hb[4], hf[4];
#pragma unroll
        for (int jj = 0; jj < 4; ++jj) {
            float iv = sigmoid_acc(sg[jj]);
            float gv = tanh_acc(sg[4 + jj]);
            float ov = sigmoid_acc(sg[8 + jj]);
            float cc = iv * gv;                 // c0 = 0 => f-gate drops out
            hb[jj] = ov * tanh_acc(cc);
            hf[jj] = g_hf[b * 4 + jj];
        }
#pragma unroll
        for (int o2 = 0; o2 < 2; ++o2) {
            float s = __ldg(&bout[o2]);
#pragma unroll
            for (int jj = 0; jj < 4; ++jj) {
                s = fmaf(__ldg(&Wout[o2 * 8 + jj]),     hf[jj], s);
                s = fmaf(__ldg(&Wout[o2 * 8 + 4 + jj]), hb[jj], s);
            }
            out[b * 2 + o2] = s;
        }
    }
}

// =====================================================================
extern "C" void kernel_launch(void* const* d_in, const int* in_sizes, int n_in,
                              void* d_out, int out_size) {
    const float* x    = (const float*)d_in[0];
    const float* Wihf = (const float*)d_in[1];
    const float* Whhf = (const float*)d_in[2];
    const float* bihf = (const float*)d_in[3];
    const float* bhhf = (const float*)d_in[4];
    const float* Wihb = (const float*)d_in[5];
    // d_in[6] = W_hh_b: provably unused (backward output only needs step 1 from zero state)
    const float* bihb = (const float*)d_in[7];
    const float* bhhb = (const float*)d_in[8];
    const float* Wout = (const float*)d_in[9];
    const float* bout = (const float*)d_in[10];
    float* out = (float*)d_out;

    fused_kernel<<<528, 128, SMEM_BYTES>>>(x, Wihf, bihf, bhhf, Whhf);
    tail_kernel<<<BATCH, 384>>>(x, Wihb, bihb, bhhb, Wout, bout, out);
}

// round 16
// speedup vs baseline: 1.4655x; 1.0785x over previous
#include <cuda_runtime.h>

// Problem constants
constexpr int BATCH = 128;
constexpr int TSEQ  = 512;
constexpr int KIN   = 906;
constexpr int NG    = 16;       // 4*H gates
constexpr int KHALF = 453;      // K split
constexpr int CK    = 16;       // k per chunk
constexpr int NCHK  = 29;       // 28*16 + 5
constexpr int PROWS = 256;      // rows per proj unit
constexpr int PITCH = 258;      // k-major tile pitch (floats)
constexpr int SMEM_BYTES = (2 * CK * PITCH + 2 * CK * 16) * 4;  // 35072 (>= lstm's 32768)

// Scratch (device globals; no allocation allowed)
// K-half partials, layout [t][b][j][ifgo]; i/f/o pre-scaled 0.5 (sigmoid fold)
__device__ __align__(16) float g_xph[2][BATCH * TSEQ * NG];
__device__ float g_hf[BATCH * 4];
__device__ float g_pre[BATCH * 12];  // backward-cell preacts [b][i0-3,g0-3,o0-3]
__device__ unsigned g_flag[32];      // [group(16)][part(2)] counters, target 16; reset by combine

// ---------- packed fp32x2 helpers (Blackwell FFMA2) ----------
__device__ __forceinline__ unsigned long long pack2(float x) {
    unsigned long long r;
    asm("mov.b64 %0, {%1, %1};" : "=l"(r) : "f"(x));
    return r;
}
__device__ __forceinline__ unsigned long long fma2(unsigned long long a,
                                                   unsigned long long b,
                                                   unsigned long long c) {
    unsigned long long d;
    asm("fma.rn.f32x2 %0, %1, %2, %3;" : "=l"(d) : "l"(a), "l"(b), "l"(c));
    return d;
}
__device__ __forceinline__ void unpack2(unsigned long long a, float& lo, float& hi) {
    asm("mov.b64 {%0, %1}, %2;" : "=f"(lo), "=f"(hi) : "l"(a));
}

// ---------- activations ----------
__device__ __forceinline__ float tanha(float x) {
    float r;
    asm("tanh.approx.f32 %0, %1;" : "=f"(r) : "f"(x));
    return r;
}
__device__ __forceinline__ float sigmoid_acc(float x) {
    float e = __expf(-x);
    return __fdividef(1.0f, 1.0f + e);
}
__device__ __forceinline__ float tanh_acc(float x) {
    float e = __expf(2.0f * x);
    return 1.0f - __fdividef(2.0f, 1.0f + e);
}

// ---------- cp.async 16B (lstm feed; .cg -> L2, coherent with fence+flag) ----------
__device__ __forceinline__ void cp16(void* dst, const void* src) {
    unsigned d = (unsigned)__cvta_generic_to_shared(dst);
    asm volatile("cp.async.cg.shared.global [%0], [%1], 16;" :: "r"(d), "l"(src));
}

// =====================================================================
// proj body (R15 verbatim)
// =====================================================================
__device__ void proj_body(float* smem, const float* __restrict__ x,
                          const float* __restrict__ Wih,
                          const float* __restrict__ bih,
                          const float* __restrict__ bhh,
                          int batch, int part, int half) {
    float* const sxT[2] = { smem, smem + CK * PITCH };
    float* const swb[2] = { smem + 2 * CK * PITCH, smem + 2 * CK * PITCH + CK * 16 };

    const int tid  = threadIdx.x;
    const int lane = tid & 31;
    const int wid  = tid >> 5;
    const int kb   = half * KHALF;
    const size_t row0 = (size_t)(batch * 2 + part) * PROWS;

    const int kk_l = lane & 15;     // k within chunk
    const int rs   = lane >> 4;     // row sub (0/1)

    unsigned long long accA[8], accB[8];
#pragma unroll
    for (int m = 0; m < 8; ++m) { accA[m] = 0ull; accB[m] = 0ull; }

    float xr0[32], xr1[32];   // STATIC depth-2 banks
    float wr0[2],  wr1[2];

    auto ldg_chunk = [&](int ch, float (&xr)[32], float (&wr)[2]) {
        const int kloc = ch * CK + kk_l;
        const bool ok = kloc < KHALF;
        const float* xp = x + (row0 + 64 * wid + rs) * KIN + kb + kloc;
#pragma unroll
        for (int i = 0; i < 32; ++i)
            xr[i] = ok ? __ldg(xp + (size_t)2 * i * KIN) : 0.0f;
#pragma unroll
        for (int u = 0; u < 2; ++u) {
            const int idx = tid + 128 * u;
            const int kw = idx >> 4, g = idx & 15;
            const int kwl = ch * CK + kw;
            const float sc = (g >= 8 && g < 12) ? 1.0f : 0.5f;
            wr[u] = (kwl < KHALF) ? sc * __ldg(Wih + (size_t)g * KIN + kb + kwl) : 0.0f;
        }
    };
    auto sts_chunk = [&](const float (&xr)[32], const float (&wr)[2], int buf) {
        float* sx = sxT[buf];
#pragma unroll
        for (int i = 0; i < 32; ++i)
            sx[kk_l * PITCH + 64 * wid + rs + 2 * i] = xr[i];
        float* swp = swb[buf];
#pragma unroll
        for (int u = 0; u < 2; ++u)
            swp[tid + 128 * u] = wr[u];    // [k][g] layout: idx = k*16+g
    };

#define PROJ_K(SX, SW, KK)                                                     \
    {                                                                          \
        const float2 xv = *(const float2*)((SX) + (KK) * PITCH + 2 * tid);     \
        const unsigned long long xa = pack2(xv.x);                             \
        const unsigned long long xb = pack2(xv.y);                             \
        const ulonglong2* wr = (const ulonglong2*)((SW) + (KK) * 16);          \
        ulonglong2 w0 = wr[0], w1 = wr[1];                                     \
        accA[0] = fma2(xa, w0.x, accA[0]);  accB[0] = fma2(xb, w0.x, accB[0]); \
        accA[1] = fma2(xa, w0.y, accA[1]);  accB[1] = fma2(xb, w0.y, accB[1]); \
        accA[2] = fma2(xa, w1.x, accA[2]);  accB[2] = fma2(xb, w1.x, accB[2]); \
        accA[3] = fma2(xa, w1.y, accA[3]);  accB[3] = fma2(xb, w1.y, accB[3]); \
        ulonglong2 w2 = wr[2], w3 = wr[3];                                     \
        accA[4] = fma2(xa, w2.x, accA[4]);  accB[4] = fma2(xb, w2.x, accB[4]); \
        accA[5] = fma2(xa, w2.y, accA[5]);  accB[5] = fma2(xb, w2.y, accB[5]); \
        accA[6] = fma2(xa, w3.x, accA[6]);  accB[6] = fma2(xb, w3.x, accB[6]); \
        accA[7] = fma2(xa, w3.y, accA[7]);  accB[7] = fma2(xb, w3.y, accB[7]); \
    }

    ldg_chunk(0, xr0, wr0);
    ldg_chunk(1, xr1, wr1);
    sts_chunk(xr0, wr0, 0);
    __syncthreads();

#pragma unroll 1
    for (int c2 = 0; c2 < 14; ++c2) {
        const int ch = 2 * c2;
        ldg_chunk(ch + 2, xr0, wr0);
        {
            const float* sx = sxT[0];
            const float* swp = swb[0];
#pragma unroll
            for (int kk = 0; kk < CK; ++kk) PROJ_K(sx, swp, kk)
        }
        sts_chunk(xr1, wr1, 1);
        __syncthreads();
        if (ch + 3 < NCHK) ldg_chunk(ch + 3, xr1, wr1);
        {
            const float* sx = sxT[1];
            const float* swp = swb[1];
#pragma unroll
            for (int kk = 0; kk < CK; ++kk) PROJ_K(sx, swp, kk)
        }
        sts_chunk(xr0, wr0, 0);
        __syncthreads();
    }
    {
        const float* sx = sxT[0];
        const float* swp = swb[0];
#pragma unroll
        for (int kk = 0; kk < KHALF - CK * (NCHK - 1); ++kk) PROJ_K(sx, swp, kk)
    }
#undef PROJ_K

    float va[16], vb[16];
#pragma unroll
    for (int m = 0; m < 8; ++m) { unpack2(accA[m], va[2*m], va[2*m+1]);
                                  unpack2(accB[m], vb[2*m], vb[2*m+1]); }
    if (half == 0) {
#pragma unroll
        for (int g = 0; g < 16; ++g) {
            const float sc = (g >= 8 && g < 12) ? 1.0f : 0.5f;
            const float b = sc * (__ldg(&bih[g]) + __ldg(&bhh[g]));
            va[g] += b; vb[g] += b;
        }
    }

    float4* dst = reinterpret_cast<float4*>(g_xph[half]);
    const size_t rA = row0 + 2 * tid;
    const size_t tA = rA & 511, bA = rA >> 9;
    const size_t tB = (rA + 1) & 511, bB = (rA + 1) >> 9;
#pragma unroll
    for (int j = 0; j < 4; ++j) {
        dst[(tA * 128 + bA) * 4 + j] = make_float4(va[j], va[4+j], va[8+j], va[12+j]);
        dst[(tB * 128 + bB) * 4 + j] = make_float4(vb[j], vb[4+j], vb[8+j], vb[12+j]);
    }

    // completion signal for the lstm consumer
    __syncthreads();
    if (tid == 0) {
        __threadfence();
        atomicAdd(&g_flag[(batch >> 3) * 2 + part], 1u);
    }
}

// =====================================================================
// lstm body (R15 verbatim). blk in [0,16): 8 batches/block;
// warp0 compute, warp1 copy (flag-gated), warps 2-3 sync-idle.
// =====================================================================
__device__ void lstm_body(float* smem, const float* __restrict__ Whh, int blk) {
    auto buf_at = [&](int p, int h, int tt, int b) -> float* {
        return smem + ((((p * 2 + h) * 16 + tt) * 8) + b) * 16;
    };

    const int tid = threadIdx.x;
    const int wid = tid >> 5;
    const int blk_b0 = blk * 8;
    const int group = blk >> 1;

    if (wid == 1) {
        // ---------------- copy warp ----------------
        const int l  = tid & 31;
        const int bb = l & 7;
        const int f0 = (l >> 3) * 4;
        auto wait_part = [&](int part) {
            volatile unsigned* f = &g_flag[group * 2 + part];
            while (*f < 16u) __nanosleep(64);
            __threadfence();
        };
        auto fill = [&](int s) {
            const int t0 = s * 16;
            const int p = s & 1;
#pragma unroll
            for (int h = 0; h < 2; ++h) {
                const float* base = g_xph[h];
#pragma unroll
                for (int tt = 0; tt < 16; ++tt) {
                    const float* src = base + (((size_t)(t0 + tt) * 128) + blk_b0 + bb) * 16 + f0;
                    cp16(buf_at(p, h, tt, bb) + f0, src);
                }
            }
        };
        wait_part(0);
        fill(0);
        asm volatile("cp.async.commit_group;");
        asm volatile("cp.async.wait_group 0;" ::: "memory");
        __syncthreads();
        for (int s = 0; s < 32; ++s) {
            if (s + 1 < 32) {
                if (s + 1 == 16) wait_part(1);
                fill(s + 1);
                asm volatile("cp.async.commit_group;");
                asm volatile("cp.async.wait_group 0;" ::: "memory");
            }
            __syncthreads();
        }
    } else if (wid == 0) {
        // ---------------- compute warp ----------------
        const int j  = tid & 3;
        const int pr = tid >> 2;
        const int bA = pr;

        // 0.25 = 0.5(sigmoid fold) * 0.5(h2 fold); g-gate 0.5 (h2 fold only)
        float wi[4], wf[4], wg[4], wo[4];
#pragma unroll
        for (int k = 0; k < 4; ++k) {
            wi[k] = 0.25f * __ldg(&Whh[(0  + j) * 4 + k]);
            wf[k] = 0.25f * __ldg(&Whh[(4  + j) * 4 + k]);
            wg[k] = 0.50f * __ldg(&Whh[(8  + j) * 4 + k]);
            wo[k] = 0.25f * __ldg(&Whh[(12 + j) * 4 + k]);
        }

        float a0 = 0.f, a1 = 0.f, a2 = 0.f, a3 = 0.f, cA = 0.f, hA2 = 0.f;

        __syncthreads();   // matches copy prologue sync

        for (int s = 0; s < 32; ++s) {
            const int p = s & 1;
            float4 cA0 = *reinterpret_cast<const float4*>(buf_at(p, 0, 0, bA) + 4 * j);
            float4 cA1 = *reinterpret_cast<const float4*>(buf_at(p, 1, 0, bA) + 4 * j);
#pragma unroll
            for (int tt = 0; tt < 16; ++tt) {
                float4 nA0, nA1;
                if (tt < 15) {
                    nA0 = *reinterpret_cast<const float4*>(buf_at(p, 0, tt + 1, bA) + 4 * j);
                    nA1 = *reinterpret_cast<const float4*>(buf_at(p, 1, tt + 1, bA) + 4 * j);
                }

                float ip = fmaf(wi[1], a1, fmaf(wi[0], a0, cA0.x)) + fmaf(wi[3], a3, fmaf(wi[2], a2, cA1.x));
                float fp = fmaf(wf[1], a1, fmaf(wf[0], a0, cA0.y)) + fmaf(wf[3], a3, fmaf(wf[2], a2, cA1.y));
                float gp = fmaf(wg[1], a1, fmaf(wg[0], a0, cA0.z)) + fmaf(wg[3], a3, fmaf(wg[2], a2, cA1.z));
                float op = fmaf(wo[1], a1, fmaf(wo[0], a0, cA0.w)) + fmaf(wo[3], a3, fmaf(wo[2], a2, cA1.w));

                const float ti = tanha(ip), tf = tanha(fp), tg = tanha(gp), to = tanha(op);

                cA = 0.5f * (fmaf(tf, cA, cA) + fmaf(ti, tg, tg));

                const float tc = tanha(cA);
                hA2 = fmaf(to, tc, tc);   // = 2*h

                a0 = __shfl_sync(0xffffffffu, hA2, 0, 4);
                a1 = __shfl_sync(0xffffffffu, hA2, 1, 4);
                a2 = __shfl_sync(0xffffffffu, hA2, 2, 4);
                a3 = __shfl_sync(0xffffffffu, hA2, 3, 4);

                cA0 = nA0; cA1 = nA1;
            }
            __syncthreads();
        }

        g_hf[(blk_b0 + bA) * 4 + j] = 0.5f * hA2;
    } else {
        // idle warps: participate in all 33 block syncs
        for (int i = 0; i < 33; ++i) __syncthreads();
    }
}

// =====================================================================
// backcell body: per-warp backward-cell gate reductions (depends ONLY
// on x). Warp = one batch; 12 accumulators (gate rows i:0-3, g:8-11,
// o:12-15); writes preacts (+biases) to g_pre.
// =====================================================================
__device__ void backcell_body(const float* __restrict__ x,
                              const float* __restrict__ Wihb,
                              const float* __restrict__ bihb,
                              const float* __restrict__ bhhb,
                              int blk) {
    const int tid = threadIdx.x;
    const int w = tid >> 5;
    const int l = tid & 31;
    const int b = blk * 4 + w;

    const float* xr = x + ((size_t)b * TSEQ + (TSEQ - 1)) * KIN;

    float a[12];
#pragma unroll
    for (int m = 0; m < 12; ++m) a[m] = 0.f;

    for (int k = l; k < KIN; k += 32) {
        const float xv = __ldg(&xr[k]);
#pragma unroll
        for (int m = 0; m < 12; ++m) {
            const int gr = (m < 4) ? m : (m + 4);   // 0-3, 8-11, 12-15
            a[m] = fmaf(xv, __ldg(&Wihb[(size_t)gr * KIN + k]), a[m]);
        }
    }
#pragma unroll
    for (int m = 0; m < 12; ++m) {
#pragma unroll
        for (int s = 16; s > 0; s >>= 1)
            a[m] += __shfl_xor_sync(0xffffffffu, a[m], s);
    }
    if (l < 12) {
        const int gr = (l < 4) ? l : (l + 4);
        // lane l holds nothing useful; recompute from lane 0 broadcast instead:
    }
    if (l == 0) {
#pragma unroll
        for (int m = 0; m < 12; ++m) {
            const int gr = (m < 4) ? m : (m + 4);
            g_pre[b * 12 + m] = a[m] + __ldg(&bihb[gr]) + __ldg(&bhhb[gr]);
        }
    }
}

// =====================================================================
// Kernel 1: fused proj + lstm + backcell. Grid 560 x 128 threads.
// bids 0-15: lstm. bids 16-527: proj (part-0 at low bids -> wave 1).
// bids 528-559: backcell (wave 2; only depends on x).
// =====================================================================
__global__ __launch_bounds__(128) void fused_kernel(const float* __restrict__ x,
                                                    const float* __restrict__ Wih,
                                                    const float* __restrict__ bih,
                                                    const float* __restrict__ bhh,
                                                    const float* __restrict__ Whh,
                                                    const float* __restrict__ Wihb,
                                                    const float* __restrict__ bihb,
                                                    const float* __restrict__ bhhb) {
    extern __shared__ float smem[];
    const int bid = blockIdx.x;
    if (bid >= 528) {
        backcell_body(x, Wihb, bihb, bhhb, bid - 528);
    } else if (bid >= 16) {
        const int u = bid - 16;             // 0..511
        const int part = u >> 8;            // part 0 first (low bids)
        const int v = u & 255;
        const int batch = v >> 1;
        const int half = v & 1;
        proj_body(smem, x, Wih, bih, bhh, batch, part, half);
    } else {
        lstm_body(smem, Whh, bid);
    }
}

// =====================================================================
// Kernel 2: combine. 1 block x 128 threads; thread = batch.
// hb from g_pre (c0=0 => f-gate dropped), hf from g_hf, output head.
// Accurate activations (off critical path). Also resets g_flag.
// =====================================================================
__global__ __launch_bounds__(128) void combine_kernel(const float* __restrict__ Wout,
                                                      const float* __restrict__ bout,
                                                      float* __restrict__ out) {
    const int b = threadIdx.x;

    if (b < 32) {
        // reset flags for next graph replay (safe: fused already done)
        g_flag[b] = 0u;
    }

    float hb[4], hf[4];
#pragma unroll
    for (int jj = 0; jj < 4; ++jj) {
        const float ip = g_pre[b * 12 + jj];
        const float gp = g_pre[b * 12 + 4 + jj];
        const float op = g_pre[b * 12 + 8 + jj];
        const float iv = sigmoid_acc(ip);
        const float gv = tanh_acc(gp);
        const float ov = sigmoid_acc(op);
        const float cc = iv * gv;               // c0 = 0 => f-gate drops out
        hb[jj] = ov * tanh_acc(cc);
        hf[jj] = g_hf[b * 4 + jj];
    }
#pragma unroll
    for (int o2 = 0; o2 < 2; ++o2) {
        float s = __ldg(&bout[o2]);
#pragma unroll
        for (int jj = 0; jj < 4; ++jj) {
            s = fmaf(__ldg(&Wout[o2 * 8 + jj]),     hf[jj], s);
            s = fmaf(__ldg(&Wout[o2 * 8 + 4 + jj]), hb[jj], s);
        }
        out[b * 2 + o2] = s;
    }
}

// =====================================================================
extern "C" void kernel_launch(void* const* d_in, const int* in_sizes, int n_in,
                              void* d_out, int out_size) {
    const float* x    = (const float*)d_in[0];
    const float* Wihf = (const float*)d_in[1];
    const float* Whhf = (const float*)d_in[2];
    const float* bihf = (const float*)d_in[3];
    const float* bhhf = (const float*)d_in[4];
    const float* Wihb = (const float*)d_in[5];
    // d_in[6] = W_hh_b: provably unused (backward output only needs step 1 from zero state)
    const float* bihb = (const float*)d_in[7];
    const float* bhhb = (const float*)d_in[8];
    const float* Wout = (const float*)d_in[9];
    const float* bout = (const float*)d_in[10];
    float* out = (float*)d_out;

    fused_kernel<<<560, 128, SMEM_BYTES>>>(x, Wihf, bihf, bhhf, Whhf, Wihb, bihb, bhhb);
    combine_kernel<<<1, 128>>>(Wout, bout, out);
}

// round 17
// speedup vs baseline: 1.4697x; 1.0029x over previous
#include <cuda_runtime.h>

// Problem constants
constexpr int BATCH = 128;
constexpr int TSEQ  = 512;
constexpr int KIN   = 906;
constexpr int NG    = 16;       // 4*H gates
constexpr int KHALF = 453;      // K split
constexpr int CK    = 16;       // k per chunk
constexpr int NCHK  = 29;       // 28*16 + 5
constexpr int PITCH = 258;      // k-major tile pitch (floats)
constexpr int SMEM_BYTES = (2 * CK * PITCH + 2 * CK * 16) * 4;  // 35072 (>= lstm's 32768)

// Scratch (device globals; no allocation allowed)
// K-half partials, layout [t][b][j][ifgo]; i/f/o pre-scaled 0.5 (sigmoid fold)
__device__ __align__(16) float g_xph[2][BATCH * TSEQ * NG];
__device__ float g_hf[BATCH * 4];
__device__ float g_pre[BATCH * 12];  // backward-cell preacts [b][i0-3,g0-3,o0-3]
__device__ unsigned g_flag[64];      // [group(16)][quarter(4)] counters, target 8
__device__ unsigned g_done;          // producer completion counter (target 48)

// ---------- packed fp32x2 helpers (Blackwell FFMA2) ----------
__device__ __forceinline__ unsigned long long pack2(float x) {
    unsigned long long r;
    asm("mov.b64 %0, {%1, %1};" : "=l"(r) : "f"(x));
    return r;
}
__device__ __forceinline__ unsigned long long fma2(unsigned long long a,
                                                   unsigned long long b,
                                                   unsigned long long c) {
    unsigned long long d;
    asm("fma.rn.f32x2 %0, %1, %2, %3;" : "=l"(d) : "l"(a), "l"(b), "l"(c));
    return d;
}
__device__ __forceinline__ void unpack2(unsigned long long a, float& lo, float& hi) {
    asm("mov.b64 {%0, %1}, %2;" : "=f"(lo), "=f"(hi) : "l"(a));
}

// ---------- activations ----------
__device__ __forceinline__ float tanha(float x) {
    float r;
    asm("tanh.approx.f32 %0, %1;" : "=f"(r) : "f"(x));
    return r;
}
__device__ __forceinline__ float sigmoid_acc(float x) {
    float e = __expf(-x);
    return __fdividef(1.0f, 1.0f + e);
}
__device__ __forceinline__ float tanh_acc(float x) {
    float e = __expf(2.0f * x);
    return 1.0f - __fdividef(2.0f, 1.0f + e);
}

// ---------- cp.async 16B (lstm feed; .cg -> L2, coherent with fence+flag) ----------
__device__ __forceinline__ void cp16(void* dst, const void* src) {
    unsigned d = (unsigned)__cvta_generic_to_shared(dst);
    asm volatile("cp.async.cg.shared.global [%0], [%1], 16;" :: "r"(d), "l"(src));
}

// =====================================================================
// proj body: unit = 2 batches x 128 t x half-K (256 rows).
// Same staging/compute as R15/R16 (depth-2 static register banks);
// only the row->(batch,t) mapping and the flag index changed.
// =====================================================================
__device__ void proj_body(float* smem, const float* __restrict__ x,
                          const float* __restrict__ Wih,
                          const float* __restrict__ bih,
                          const float* __restrict__ bhh,
                          int pair, int quarter, int half) {
    float* const sxT[2] = { smem, smem + CK * PITCH };
    float* const swb[2] = { smem + 2 * CK * PITCH, smem + 2 * CK * PITCH + CK * 16 };

    const int tid  = threadIdx.x;
    const int lane = tid & 31;
    const int wid  = tid >> 5;
    const int kb   = half * KHALF;

    const int kk_l = lane & 15;     // k within chunk
    const int rs   = lane >> 4;     // row sub (0/1)

    // thread's staged rows all lie in one batch:
    const int bsel = wid >> 1;                  // 0/1 -> batch 2p / 2p+1
    const int roff = 64 * (wid & 1) + rs;       // within-batch t offset base
    const float* xbase = x + (((size_t)(2 * pair + bsel) * TSEQ)
                              + quarter * 128 + roff) * KIN + kb;

    unsigned long long accA[8], accB[8];
#pragma unroll
    for (int m = 0; m < 8; ++m) { accA[m] = 0ull; accB[m] = 0ull; }

    float xr0[32], xr1[32];   // STATIC depth-2 banks
    float wr0[2],  wr1[2];

    auto ldg_chunk = [&](int ch, float (&xr)[32], float (&wr)[2]) {
        const int kloc = ch * CK + kk_l;
        const bool ok = kloc < KHALF;
        const float* xp = xbase + kloc;
#pragma unroll
        for (int i = 0; i < 32; ++i)
            xr[i] = ok ? __ldg(xp + (size_t)2 * i * KIN) : 0.0f;
#pragma unroll
        for (int u = 0; u < 2; ++u) {
            const int idx = tid + 128 * u;
            const int kw = idx >> 4, g = idx & 15;
            const int kwl = ch * CK + kw;
            const float sc = (g >= 8 && g < 12) ? 1.0f : 0.5f;
            wr[u] = (kwl < KHALF) ? sc * __ldg(Wih + (size_t)g * KIN + kb + kwl) : 0.0f;
        }
    };
    auto sts_chunk = [&](const float (&xr)[32], const float (&wr)[2], int buf) {
        float* sx = sxT[buf];
#pragma unroll
        for (int i = 0; i < 32; ++i)
            sx[kk_l * PITCH + 64 * wid + rs + 2 * i] = xr[i];
        float* swp = swb[buf];
#pragma unroll
        for (int u = 0; u < 2; ++u)
            swp[tid + 128 * u] = wr[u];    // [k][g] layout: idx = k*16+g
    };

#define PROJ_K(SX, SW, KK)                                                     \
    {                                                                          \
        const float2 xv = *(const float2*)((SX) + (KK) * PITCH + 2 * tid);     \
        const unsigned long long xa = pack2(xv.x);                             \
        const unsigned long long xb = pack2(xv.y);                             \
        const ulonglong2* wr = (const ulonglong2*)((SW) + (KK) * 16);          \
        ulonglong2 w0 = wr[0], w1 = wr[1];                                     \
        accA[0] = fma2(xa, w0.x, accA[0]);  accB[0] = fma2(xb, w0.x, accB[0]); \
        accA[1] = fma2(xa, w0.y, accA[1]);  accB[1] = fma2(xb, w0.y, accB[1]); \
        accA[2] = fma2(xa, w1.x, accA[2]);  accB[2] = fma2(xb, w1.x, accB[2]); \
        accA[3] = fma2(xa, w1.y, accA[3]);  accB[3] = fma2(xb, w1.y, accB[3]); \
        ulonglong2 w2 = wr[2], w3 = wr[3];                                     \
        accA[4] = fma2(xa, w2.x, accA[4]);  accB[4] = fma2(xb, w2.x, accB[4]); \
        accA[5] = fma2(xa, w2.y, accA[5]);  accB[5] = fma2(xb, w2.y, accB[5]); \
        accA[6] = fma2(xa, w3.x, accA[6]);  accB[6] = fma2(xb, w3.x, accB[6]); \
        accA[7] = fma2(xa, w3.y, accA[7]);  accB[7] = fma2(xb, w3.y, accB[7]); \
    }

    ldg_chunk(0, xr0, wr0);
    ldg_chunk(1, xr1, wr1);
    sts_chunk(xr0, wr0, 0);
    __syncthreads();

#pragma unroll 1
    for (int c2 = 0; c2 < 14; ++c2) {
        const int ch = 2 * c2;
        ldg_chunk(ch + 2, xr0, wr0);
        {
            const float* sx = sxT[0];
            const float* swp = swb[0];
#pragma unroll
            for (int kk = 0; kk < CK; ++kk) PROJ_K(sx, swp, kk)
        }
        sts_chunk(xr1, wr1, 1);
        __syncthreads();
        if (ch + 3 < NCHK) ldg_chunk(ch + 3, xr1, wr1);
        {
            const float* sx = sxT[1];
            const float* swp = swb[1];
#pragma unroll
            for (int kk = 0; kk < CK; ++kk) PROJ_K(sx, swp, kk)
        }
        sts_chunk(xr0, wr0, 0);
        __syncthreads();
    }
    {
        const float* sx = sxT[0];
        const float* swp = swb[0];
#pragma unroll
        for (int kk = 0; kk < KHALF - CK * (NCHK - 1); ++kk) PROJ_K(sx, swp, kk)
    }
#undef PROJ_K

    float va[16], vb[16];
#pragma unroll
    for (int m = 0; m < 8; ++m) { unpack2(accA[m], va[2*m], va[2*m+1]);
                                  unpack2(accB[m], vb[2*m], vb[2*m+1]); }
    if (half == 0) {
#pragma unroll
        for (int g = 0; g < 16; ++g) {
            const float sc = (g >= 8 && g < 12) ? 1.0f : 0.5f;
            const float b = sc * (__ldg(&bih[g]) + __ldg(&bhh[g]));
            va[g] += b; vb[g] += b;
        }
    }

    // this thread's rows: local 2*tid, 2*tid+1 -> batch 2p+(tid>=64),
    // t = quarter*128 + (2*tid mod 128) and t+1
    float4* dst = reinterpret_cast<float4*>(g_xph[half]);
    const size_t bidx = 2 * pair + (tid >> 6);
    const size_t tA = quarter * 128 + ((2 * tid) & 127);
    const size_t tB = tA + 1;
#pragma unroll
    for (int j = 0; j < 4; ++j) {
        dst[(tA * 128 + bidx) * 4 + j] = make_float4(va[j], va[4+j], va[8+j], va[12+j]);
        dst[(tB * 128 + bidx) * 4 + j] = make_float4(vb[j], vb[4+j], vb[8+j], vb[12+j]);
    }

    // completion signal for the lstm consumer: [group][quarter], target 8
    __syncthreads();
    if (tid == 0) {
        __threadfence();
        atomicAdd(&g_flag[(pair >> 2) * 4 + quarter], 1u);
    }
}

// =====================================================================
// lstm body. blk in [0,16): 8 batches/block; warp0 compute, warp1 copy
// (quarter-flag gated), warps 2-3 sync-idle.
// =====================================================================
__device__ void lstm_body(float* smem, const float* __restrict__ Whh, int blk) {
    auto buf_at = [&](int p, int h, int tt, int b) -> float* {
        return smem + ((((p * 2 + h) * 16 + tt) * 8) + b) * 16;
    };

    const int tid = threadIdx.x;
    const int wid = tid >> 5;
    const int blk_b0 = blk * 8;
    const int group = blk >> 1;

    if (wid == 1) {
        // ---------------- copy warp ----------------
        const int l  = tid & 31;
        const int bb = l & 7;
        const int f0 = (l >> 3) * 4;
        auto wait_quarter = [&](int q) {
            volatile unsigned* f = &g_flag[group * 4 + q];
            while (*f < 8u) __nanosleep(64);
            __threadfence();
        };
        auto fill = [&](int s) {
            const int t0 = s * 16;
            const int p = s & 1;
#pragma unroll
            for (int h = 0; h < 2; ++h) {
                const float* base = g_xph[h];
#pragma unroll
                for (int tt = 0; tt < 16; ++tt) {
                    const float* src = base + (((size_t)(t0 + tt) * 128) + blk_b0 + bb) * 16 + f0;
                    cp16(buf_at(p, h, tt, bb) + f0, src);
                }
            }
        };
        wait_quarter(0);
        fill(0);
        asm volatile("cp.async.commit_group;");
        asm volatile("cp.async.wait_group 0;" ::: "memory");
        __syncthreads();
        for (int s = 0; s < 32; ++s) {
            if (s + 1 < 32) {
                if (((s + 1) & 7) == 0) wait_quarter((s + 1) >> 3);
                fill(s + 1);
                asm volatile("cp.async.commit_group;");
                asm volatile("cp.async.wait_group 0;" ::: "memory");
            }
            __syncthreads();
        }
    } else if (wid == 0) {
        // ---------------- compute warp ----------------
        const int j  = tid & 3;
        const int pr = tid >> 2;
        const int bA = pr;

        // 0.25 = 0.5(sigmoid fold) * 0.5(h2 fold); g-gate 0.5 (h2 fold only)
        float wi[4], wf[4], wg[4], wo[4];
#pragma unroll
        for (int k = 0; k < 4; ++k) {
            wi[k] = 0.25f * __ldg(&Whh[(0  + j) * 4 + k]);
            wf[k] = 0.25f * __ldg(&Whh[(4  + j) * 4 + k]);
            wg[k] = 0.50f * __ldg(&Whh[(8  + j) * 4 + k]);
            wo[k] = 0.25f * __ldg(&Whh[(12 + j) * 4 + k]);
        }

        float a0 = 0.f, a1 = 0.f, a2 = 0.f, a3 = 0.f, cA = 0.f, hA2 = 0.f;

        __syncthreads();   // matches copy prologue sync

        for (int s = 0; s < 32; ++s) {
            const int p = s & 1;
            float4 cA0 = *reinterpret_cast<const float4*>(buf_at(p, 0, 0, bA) + 4 * j);
            float4 cA1 = *reinterpret_cast<const float4*>(buf_at(p, 1, 0, bA) + 4 * j);
#pragma unroll
            for (int tt = 0; tt < 16; ++tt) {
                float4 nA0, nA1;
                if (tt < 15) {
                    nA0 = *reinterpret_cast<const float4*>(buf_at(p, 0, tt + 1, bA) + 4 * j);
                    nA1 = *reinterpret_cast<const float4*>(buf_at(p, 1, tt + 1, bA) + 4 * j);
                }

                float ip = fmaf(wi[1], a1, fmaf(wi[0], a0, cA0.x)) + fmaf(wi[3], a3, fmaf(wi[2], a2, cA1.x));
                float fp = fmaf(wf[1], a1, fmaf(wf[0], a0, cA0.y)) + fmaf(wf[3], a3, fmaf(wf[2], a2, cA1.y));
                float gp = fmaf(wg[1], a1, fmaf(wg[0], a0, cA0.z)) + fmaf(wg[3], a3, fmaf(wg[2], a2, cA1.z));
                float op = fmaf(wo[1], a1, fmaf(wo[0], a0, cA0.w)) + fmaf(wo[3], a3, fmaf(wo[2], a2, cA1.w));

                const float ti = tanha(ip), tf = tanha(fp), tg = tanha(gp), to = tanha(op);

                cA = 0.5f * (fmaf(tf, cA, cA) + fmaf(ti, tg, tg));

                const float tc = tanha(cA);
                hA2 = fmaf(to, tc, tc);   // = 2*h

                a0 = __shfl_sync(0xffffffffu, hA2, 0, 4);
                a1 = __shfl_sync(0xffffffffu, hA2, 1, 4);
                a2 = __shfl_sync(0xffffffffu, hA2, 2, 4);
                a3 = __shfl_sync(0xffffffffu, hA2, 3, 4);

                cA0 = nA0; cA1 = nA1;
            }
            __syncthreads();
        }

        g_hf[(blk_b0 + bA) * 4 + j] = 0.5f * hA2;
    } else {
        // idle warps: participate in all 33 block syncs
        for (int i = 0; i < 33; ++i) __syncthreads();
    }
}

// =====================================================================
// backcell body: per-warp backward-cell gate reductions (depends ONLY
// on x). Warp = one batch; 12 accumulators (gate rows i:0-3, g:8-11,
// o:12-15); writes preacts (+biases) to g_pre.
// =====================================================================
__device__ void backcell_body(const float* __restrict__ x,
                              const float* __restrict__ Wihb,
                              const float* __restrict__ bihb,
                              const float* __restrict__ bhhb,
                              int blk) {
    const int tid = threadIdx.x;
    const int w = tid >> 5;
    const int l = tid & 31;
    const int b = blk * 4 + w;

    const float* xr = x + ((size_t)b * TSEQ + (TSEQ - 1)) * KIN;

    float a[12];
#pragma unroll
    for (int m = 0; m < 12; ++m) a[m] = 0.f;

    for (int k = l; k < KIN; k += 32) {
        const float xv = __ldg(&xr[k]);
#pragma unroll
        for (int m = 0; m < 12; ++m) {
            const int gr = (m < 4) ? m : (m + 4);   // 0-3, 8-11, 12-15
            a[m] = fmaf(xv, __ldg(&Wihb[(size_t)gr * KIN + k]), a[m]);
        }
    }
#pragma unroll
    for (int m = 0; m < 12; ++m) {
#pragma unroll
        for (int s = 16; s > 0; s >>= 1)
            a[m] += __shfl_xor_sync(0xffffffffu, a[m], s);
    }
    if (l == 0) {
#pragma unroll
        for (int m = 0; m < 12; ++m) {
            const int gr = (m < 4) ? m : (m + 4);
            g_pre[b * 12 + m] = a[m] + __ldg(&bihb[gr]) + __ldg(&bhhb[gr]);
        }
    }
}

// =====================================================================
// Kernel: fused proj + lstm + backcell + inline combine.
// Grid 560 x 128. bids 0-15: lstm. bids 16-527: proj ordered by
// t-quarter (q0 lowest -> wave 1). bids 528-559: backcell.
// Last of the 48 producer blocks (lstm+backcell) runs the combine.
// =====================================================================
__global__ __launch_bounds__(128) void fused_kernel(const float* __restrict__ x,
                                                    const float* __restrict__ Wih,
                                                    const float* __restrict__ bih,
                                                    const float* __restrict__ bhh,
                                                    const float* __restrict__ Whh,
                                                    const float* __restrict__ Wihb,
                                                    const float* __restrict__ bihb,
                                                    const float* __restrict__ bhhb,
                                                    const float* __restrict__ Wout,
                                                    const float* __restrict__ bout,
                                                    float* __restrict__ out) {
    extern __shared__ float smem[];
    __shared__ int winner;
    const int bid = blockIdx.x;
    const int tid = threadIdx.x;

    bool producer = false;
    if (bid >= 528) {
        backcell_body(x, Wihb, bihb, bhhb, bid - 528);
        producer = true;
    } else if (bid >= 16) {
        const int u = bid - 16;             // 0..511
        const int quarter = u >> 7;         // q0 at lowest bids
        const int v = u & 127;
        const int pair = v >> 1;
        const int half = v & 1;
        proj_body(smem, x, Wih, bih, bhh, pair, quarter, half);
    } else {
        lstm_body(smem, Whh, bid);
        producer = true;
    }

    if (!producer) return;

    // ---- producer completion protocol: last arriver combines ----
    __syncthreads();
    if (tid == 0) {
        __threadfence();
        const unsigned old = atomicAdd(&g_done, 1u);
        winner = (old == 47u) ? 1 : 0;
    }
    __syncthreads();
    if (!winner) return;
    __threadfence();   // acquire: see all g_hf / g_pre writes

    // ---- inline combine (thread = batch) ----
    {
        const int b = tid;
        float hb[4], hf[4];
#pragma unroll
        for (int jj = 0; jj < 4; ++jj) {
            const float ip = g_pre[b * 12 + jj];
            const float gp = g_pre[b * 12 + 4 + jj];
            const float op = g_pre[b * 12 + 8 + jj];
            const float iv = sigmoid_acc(ip);
            const float gv = tanh_acc(gp);
            const float ov = sigmoid_acc(op);
            const float cc = iv * gv;               // c0 = 0 => f-gate drops out
            hb[jj] = ov * tanh_acc(cc);
            hf[jj] = g_hf[b * 4 + jj];
        }
#pragma unroll
        for (int o2 = 0; o2 < 2; ++o2) {
            float s = __ldg(&bout[o2]);
#pragma unroll
            for (int jj = 0; jj < 4; ++jj) {
                s = fmaf(__ldg(&Wout[o2 * 8 + jj]),     hf[jj], s);
                s = fmaf(__ldg(&Wout[o2 * 8 + 4 + jj]), hb[jj], s);
            }
            out[b * 2 + o2] = s;
        }
    }

    // ---- reset counters for the next graph replay ----
    if (tid < 64) g_flag[tid] = 0u;
    if (tid == 127) g_done = 0u;
}

// =====================================================================
extern "C" void kernel_launch(void* const* d_in, const int* in_sizes, int n_in,
                              void* d_out, int out_size) {
    const float* x    = (const float*)d_in[0];
    const float* Wihf = (const float*)d_in[1];
    const float* Whhf = (const float*)d_in[2];
    const float* bihf = (const float*)d_in[3];
    const float* bhhf = (const float*)d_in[4];
    const float* Wihb = (const float*)d_in[5];
    // d_in[6] = W_hh_b: provably unused (backward output only needs step 1 from zero state)
    const float* bihb = (const float*)d_in[7];
    const float* bhhb = (const float*)d_in[8];
    const float* Wout = (const float*)d_in[9];
    const float* bout = (const float*)d_in[10];
    float* out = (float*)d_out;

    fused_kernel<<<560, 128, SMEM_BYTES>>>(x, Wihf, bihf, bhhf, Whhf,
                                           Wihb, bihb, bhhb, Wout, bout, out);
}